// round 14
// baseline (speedup 1.0000x reference)
#include <cuda_runtime.h>
#include <cuda_fp16.h>
#include <math.h>
#include <stdint.h>

// ---------------- problem constants ----------------
#define NMAX 20000
#define EMAX 320000
#define DIM 256
#define HEADS 8

// ---------------- scratch ----------------
__device__ __align__(16) __half g_xlr[NMAX * 512];      // fp16: [n,0:256]=xl, [n,256:512]=xr
__device__ __align__(16) float g_h1[NMAX * DIM];
__device__ __align__(16) float g_z[NMAX * DIM];
__device__ __align__(16) float g_tmp[NMAX * DIM];
// fp16 activation copies (GEMM A operands)
__device__ __align__(16) __half g_h0h[NMAX * 64];
__device__ __align__(16) __half g_h1h[NMAX * DIM];
__device__ __align__(16) __half g_zh[NMAX * DIM];
__device__ __align__(16) __half g_z2h[NMAX * DIM];
__device__ __align__(16) __half g_outh[NMAX * DIM];
// CSR by dst
__device__ int   g_deg[NMAX];
__device__ int   g_cur[NMAX];
__device__ int   g_off[NMAX + 1];
__device__ int   g_bsum[32];
__device__ int   g_sync[40];               // [0]=hist done counter, [1..32]=chunk flags
__device__ int2  g_epack[EMAX];            // .x = src, .y = float bits of edge_attr
// fp16 transposed weights
#define WTH_L1  0
#define WTH_DN  32768
#define WTH_L2  98304
#define WTH_UP  229376
#define WTH_CLS 294912
#define WTH_TOTAL (294912 + 256000)
__device__ __align__(16) __half g_wth[WTH_TOTAL];

#define SCAN_CHUNK 2048

// ---------------- helpers ----------------
__device__ __forceinline__ float warpReduceSum(float v) {
#pragma unroll
    for (int o = 16; o > 0; o >>= 1) v += __shfl_xor_sync(0xffffffffu, v, o);
    return v;
}

__device__ __forceinline__ float leaky(float v) { return v > 0.f ? v : 0.2f * v; }

__device__ __forceinline__ uint32_t smem_u32(const void* p) {
    uint32_t a;
    asm("{ .reg .u64 t; cvta.to.shared.u64 t, %1; cvt.u32.u64 %0, t; }" : "=r"(a) : "l"(p));
    return a;
}

__device__ __forceinline__ void cpasync16(uint32_t dst, const void* src, bool valid) {
    int sz = valid ? 16 : 0;
    asm volatile("cp.async.cg.shared.global [%0], [%1], 16, %2;"
                 :: "r"(dst), "l"(src), "r"(sz));
}
__device__ __forceinline__ void cpasync_commit() { asm volatile("cp.async.commit_group;"); }
__device__ __forceinline__ void cpasync_wait0() { asm volatile("cp.async.wait_group 0;"); }

#define LDMATRIX_X4(r0, r1, r2, r3, addr) \
    asm volatile("ldmatrix.sync.aligned.m8n8.x4.shared.b16 {%0,%1,%2,%3}, [%4];" \
                 : "=r"(r0), "=r"(r1), "=r"(r2), "=r"(r3) : "r"(addr))

__device__ __forceinline__ int ldcg_i(const int* p) {
    int v;
    asm volatile("ld.global.cg.b32 %0, [%1];" : "=r"(v) : "l"(p));
    return v;
}

// ---------------- fused prologue: zero(deg,cur,sync) + transpose-all + inproj ----------
struct TransDesc { const float* in; __half* out; int Kreal, Kpad, N, blkStart, nx; };
struct PrologueArgs {
    TransDesc d[7];
    int tcum;
    int zb;
    int* deg; int* cur; int* sync;
    const float* x; const float* W_in; const float* b_in; __half* h0h;
    int n;
};

__global__ void prologue_kernel(PrologueArgs pa) {
    __shared__ float sbuf[32 * 33];
    int bid = blockIdx.x;
    int tid = threadIdx.x;
    if (bid < pa.zb) {
        int i = bid * 256 + tid;
        int n2 = pa.n * 2;
        if (i < n2) {
            if (i < pa.n) pa.deg[i] = 0;
            else pa.cur[i - pa.n] = 0;
        }
        if (bid == 0 && tid < 40) pa.sync[tid] = 0;
        return;
    }
    bid -= pa.zb;
    if (bid < pa.tcum) {
        float (*t)[33] = (float(*)[33])sbuf;
        int di = 0;
#pragma unroll
        for (int i = 1; i < 7; i++) if (bid >= pa.d[i].blkStart) di = i;
        const TransDesc& D = pa.d[di];
        int rem = bid - D.blkStart;
        int bx = (rem % D.nx) * 32, by = (rem / D.nx) * 32;
        int tx = tid & 31, ty = tid >> 5;
        int x = bx + tx, y = by + ty;
#pragma unroll
        for (int i = 0; i < 32; i += 8)
            t[ty + i][tx] = (x < D.N && y + i < D.Kreal) ? D.in[(size_t)(y + i) * D.N + x] : 0.f;
        __syncthreads();
        x = by + tx;
        y = bx + ty;
#pragma unroll
        for (int i = 0; i < 32; i += 8)
            if (x < D.Kpad && y + i < D.N)
                D.out[(size_t)(y + i) * D.Kpad + x] = __float2half(t[tx][ty + i]);
        return;
    }
    bid -= pa.tcum;
    {
        float* sW = sbuf;
        float* sb = sbuf + 576;
        for (int i = tid; i < 18 * 32; i += 256) sW[i] = pa.W_in[i];
        if (tid < 32) sb[tid] = pa.b_in[tid];
        __syncthreads();
        int row = bid * 8 + (tid >> 5);
        int col = tid & 31;
        if (row >= pa.n) return;
        const float* xr = pa.x + (size_t)row * 18;
        float v = sb[col];
#pragma unroll
        for (int k = 0; k < 18; k++) v += xr[k] * sW[k * 32 + col];
        pa.h0h[(size_t)row * 64 + col] = __float2half(v);
        pa.h0h[(size_t)row * 64 + 32 + col] = __float2half(0.f);
    }
}

// ---------------- fused CSR build: hist + two-level scan in ONE kernel ----------------
__global__ void csr_build_kernel(const int* __restrict__ dst, int* __restrict__ deg,
                                 int* __restrict__ off, int* __restrict__ bsum,
                                 int* __restrict__ syn, int HB, int n, int E) {
    int bid = blockIdx.x;
    int tid = threadIdx.x;
    if (bid < HB) {
        int e = bid * 256 + tid;
        if (e < E) atomicAdd(&deg[dst[e]], 1);
        __threadfence();
        __syncthreads();
        if (tid == 0) atomicAdd(&syn[0], 1);
        return;
    }
    int b = bid - HB;
    if (tid == 0) { while (atomicAdd(&syn[0], 0) < HB) { } }
    __syncthreads();
    __shared__ int wsum[8];
    __shared__ int pre_s;
    int base = b * SCAN_CHUNK + tid * 8;
    int e8[8];
    int s = 0;
#pragma unroll
    for (int k = 0; k < 8; k++) {
        int i = base + k;
        int v = (i < n) ? ldcg_i(&deg[i]) : 0;
        e8[k] = s;
        s += v;
    }
    int x = s;
#pragma unroll
    for (int o = 1; o < 32; o <<= 1) {
        int y = __shfl_up_sync(0xffffffffu, x, o);
        if ((tid & 31) >= o) x += y;
    }
    if ((tid & 31) == 31) wsum[tid >> 5] = x;
    __syncthreads();
    if (tid < 8) {
        int t = wsum[tid];
#pragma unroll
        for (int o = 1; o < 8; o <<= 1) {
            int y = __shfl_up_sync(0xffu, t, o);
            if (tid >= o) t += y;
        }
        wsum[tid] = t;
    }
    __syncthreads();
    int thrOff = (x - s) + ((tid >= 32) ? wsum[(tid >> 5) - 1] : 0);
    if (tid == 255) {
        bsum[b] = thrOff + s;
        __threadfence();
        atomicExch(&syn[1 + b], 1);
    }
    if (tid < 32) {
        int v = 0;
        if (tid < b) {
            while (atomicAdd(&syn[1 + tid], 0) == 0) { }
            v = atomicAdd(&bsum[tid], 0);
        }
#pragma unroll
        for (int o = 16; o > 0; o >>= 1) v += __shfl_xor_sync(0xffffffffu, v, o);
        if (tid == 0) pre_s = v;
    }
    __syncthreads();
    int pre = pre_s;
#pragma unroll
    for (int k = 0; k < 8; k++) {
        int i = base + k;
        if (i < n) off[i] = pre + thrOff + e8[k];
    }
    if (b == 0 && tid == 0) off[n] = E;
}

// ---------------- scatter: 4 edges/thread, front-batched loads (MLP=4) ----------------
__global__ void scatter_kernel(const int* __restrict__ src, const int* __restrict__ dst,
                               const float* __restrict__ ea, const int* __restrict__ off,
                               int* __restrict__ cur, int2* __restrict__ epack, int E) {
    int base = blockIdx.x * 1024 + threadIdx.x;
    int d[4], s4[4];
    float a4[4];
    bool ok[4];
#pragma unroll
    for (int k = 0; k < 4; k++) {
        int e = base + k * 256;
        ok[k] = (e < E);
        if (ok[k]) { d[k] = dst[e]; s4[k] = src[e]; a4[k] = ea[e]; }
    }
    int o4[4];
#pragma unroll
    for (int k = 0; k < 4; k++)
        if (ok[k]) o4[k] = off[d[k]];
#pragma unroll
    for (int k = 0; k < 4; k++) {
        if (ok[k]) {
            int pos = o4[k] + atomicAdd(&cur[d[k]], 1);
            epack[pos] = make_int2(s4[k], __float_as_int(a4[k]));
        }
    }
}

// ---------------- fp16 mma.sync GEMM: out = A[M,K] @ WT[N,K]^T (+bias), fp32 accum ------
#define SWW 36
#define CHUNK_WORDS (128 * SWW)

extern __shared__ uint32_t g_dynsmem_u[];

__global__ __launch_bounds__(256)
void mma_gemm_h(const __half* __restrict__ A, const __half* __restrict__ WT,
                const float* __restrict__ bias, float* __restrict__ C32,
                __half* __restrict__ C16, int M, int N, int K) {
    const int tid = threadIdx.x;
    const int wid = tid >> 5, lane = tid & 31;
    const int gid = lane >> 2, tig = lane & 3;
    const int wm = (wid >> 2) * 64, wn = (wid & 3) * 32;
    const int m0 = blockIdx.y * 128, n0 = blockIdx.x * 128;

    float acc[4][4][4];
#pragma unroll
    for (int mi = 0; mi < 4; mi++)
#pragma unroll
        for (int ni = 0; ni < 4; ni++)
#pragma unroll
            for (int q = 0; q < 4; q++) acc[mi][ni][q] = 0.f;

    const int nc = (K + 63) >> 6;
    uint32_t aAddr[2], bAddr[2];
    aAddr[0] = smem_u32(g_dynsmem_u);
    bAddr[0] = aAddr[0] + CHUNK_WORDS * 4;
    aAddr[1] = aAddr[0] + 2 * CHUNK_WORDS * 4;
    bAddr[1] = aAddr[0] + 3 * CHUNK_WORDS * 4;

    const uint32_t aOff = (uint32_t)((wm + (lane & 15)) * 144 + (lane >> 4) * 16);
    const uint32_t bOff = (uint32_t)((wn + (lane & 7) + ((lane >> 4) << 3)) * 144
                                     + ((lane >> 3) & 1) * 16);

    auto issue = [&](int c, int b) {
        int k0 = c << 6;
        int Kc = K - k0; if (Kc > 64) Kc = 64;
#pragma unroll
        for (int i = 0; i < 4; i++) {
            int idx = tid + i * 256;
            int row = idx >> 3, q = idx & 7;
            uint32_t soff = (uint32_t)(row * 144 + q * 16);
            bool kv = (q * 8) < Kc;
            cpasync16(aAddr[b] + soff, A + (size_t)(m0 + row) * K + k0 + q * 8,
                      kv && (m0 + row < M));
            cpasync16(bAddr[b] + soff, WT + (size_t)(n0 + row) * K + k0 + q * 8,
                      kv && (n0 + row < N));
        }
        cpasync_commit();
    };

    issue(0, 0);
    for (int c = 0; c < nc; c++) {
        int cur = c & 1;
        cpasync_wait0();
        __syncthreads();
        if (c + 1 < nc) issue(c + 1, cur ^ 1);
        uint32_t aB = aAddr[cur] + aOff;
        uint32_t bB = bAddr[cur] + bOff;
        int Kc = K - (c << 6); if (Kc > 64) Kc = 64;
#pragma unroll
        for (int ks = 0; ks < 4; ks++) {
            if (ks * 16 < Kc) {
                uint32_t af[4][4], bf[4][2];
#pragma unroll
                for (int mi = 0; mi < 4; mi++)
                    LDMATRIX_X4(af[mi][0], af[mi][1], af[mi][2], af[mi][3],
                                aB + mi * 16 * 144 + ks * 32);
#pragma unroll
                for (int np = 0; np < 2; np++)
                    LDMATRIX_X4(bf[2 * np][0], bf[2 * np][1], bf[2 * np + 1][0], bf[2 * np + 1][1],
                                bB + np * 16 * 144 + ks * 32);
#pragma unroll
                for (int mi = 0; mi < 4; mi++)
#pragma unroll
                    for (int ni = 0; ni < 4; ni++) {
                        asm volatile(
                            "mma.sync.aligned.m16n8k16.row.col.f32.f16.f16.f32 "
                            "{%0,%1,%2,%3}, {%4,%5,%6,%7}, {%8,%9}, {%0,%1,%2,%3};"
                            : "+f"(acc[mi][ni][0]), "+f"(acc[mi][ni][1]),
                              "+f"(acc[mi][ni][2]), "+f"(acc[mi][ni][3])
                            : "r"(af[mi][0]), "r"(af[mi][1]), "r"(af[mi][2]), "r"(af[mi][3]),
                              "r"(bf[ni][0]), "r"(bf[ni][1]));
                    }
            }
        }
    }

#pragma unroll
    for (int mi = 0; mi < 4; mi++) {
        int r0 = m0 + wm + mi * 16 + gid;
        int r1 = r0 + 8;
#pragma unroll
        for (int ni = 0; ni < 4; ni++) {
            int col = n0 + wn + ni * 8 + tig * 2;
            if (col >= N) continue;
            if (C16) {
                if (r0 < M)
                    *(__half2*)(C16 + (size_t)r0 * N + col) =
                        __floats2half2_rn(acc[mi][ni][0], acc[mi][ni][1]);
                if (r1 < M)
                    *(__half2*)(C16 + (size_t)r1 * N + col) =
                        __floats2half2_rn(acc[mi][ni][2], acc[mi][ni][3]);
            } else {
                float bx = 0.f, by = 0.f;
                if (bias) { bx = bias[col]; by = bias[col + 1]; }
                if (r0 < M)
                    *(float2*)(C32 + (size_t)r0 * N + col) =
                        make_float2(acc[mi][ni][0] + bx, acc[mi][ni][1] + by);
                if (r1 < M)
                    *(float2*)(C32 + (size_t)r1 * N + col) =
                        make_float2(acc[mi][ni][2] + bx, acc[mi][ni][3] + by);
            }
        }
    }
}

// ---------------- fused CSR gather GAT + LayerNorm (fp16 xlr), prefetch depth 2 ---------
__global__ void gatln_kernel(const __half* __restrict__ xlr,
                             const int* __restrict__ off, const int2* __restrict__ epack,
                             const float* __restrict__ We, const float* __restrict__ att,
                             const float* __restrict__ bias, const float* __restrict__ res,
                             const float* __restrict__ lng, const float* __restrict__ lnb,
                             float* __restrict__ out32, __half* __restrict__ out16, int n) {
    int d = (blockIdx.x * blockDim.x + threadIdx.x) >> 5;
    int lane = threadIdx.x & 31;
    if (d >= n) return;
    float r[8], w[8], t[8];
    {
        uint4 rv = ((const uint4*)(xlr + (size_t)d * 512 + 256))[lane];
        const __half2* hp = (const __half2*)&rv;
#pragma unroll
        for (int k = 0; k < 4; k++) {
            float2 f = __half22float2(hp[k]);
            r[2 * k] = f.x; r[2 * k + 1] = f.y;
        }
        float4 wa = ((const float4*)We)[2 * lane], wb = ((const float4*)We)[2 * lane + 1];
        w[0] = wa.x; w[1] = wa.y; w[2] = wa.z; w[3] = wa.w;
        w[4] = wb.x; w[5] = wb.y; w[6] = wb.z; w[7] = wb.w;
        float4 ta = ((const float4*)att)[2 * lane], tb = ((const float4*)att)[2 * lane + 1];
        t[0] = ta.x; t[1] = ta.y; t[2] = ta.z; t[3] = ta.w;
        t[4] = tb.x; t[5] = tb.y; t[6] = tb.z; t[7] = tb.w;
    }
    float acc[8];
#pragma unroll
    for (int k = 0; k < 8; k++) acc[k] = 0.f;
    float ss = 0.f;
    int beg = off[d], cnt = off[d + 1] - beg;
    const int2* ep = epack + beg;
    if (cnt > 0) {
        // software pipeline, depth 2
        uint4 lv0, lv1;
        float aa0 = 0.f, aa1 = 0.f;
        {
            int2 pk = ep[0];
            lv0 = ((const uint4*)(xlr + (size_t)pk.x * 512))[lane];
            aa0 = __int_as_float(pk.y);
        }
        if (cnt > 1) {
            int2 pk = ep[1];
            lv1 = ((const uint4*)(xlr + (size_t)pk.x * 512))[lane];
            aa1 = __int_as_float(pk.y);
        }
        for (int i = 0; i < cnt; i++) {
            uint4 cv = lv0;
            float ca = aa0;
            lv0 = lv1; aa0 = aa1;
            if (i + 2 < cnt) {
                int2 p2 = ep[i + 2];
                lv1 = ((const uint4*)(xlr + (size_t)p2.x * 512))[lane];
                aa1 = __int_as_float(p2.y);
            }
            float l[8];
            const __half2* hp = (const __half2*)&cv;
#pragma unroll
            for (int k = 0; k < 4; k++) {
                float2 f = __half22float2(hp[k]);
                l[2 * k] = f.x; l[2 * k + 1] = f.y;
            }
            float p = 0.f;
#pragma unroll
            for (int k = 0; k < 8; k++) p += leaky(l[k] + r[k] + ca * w[k]) * t[k];
            p += __shfl_xor_sync(0xffffffffu, p, 1);
            p += __shfl_xor_sync(0xffffffffu, p, 2);
            float e = __expf(p);
#pragma unroll
            for (int k = 0; k < 8; k++) acc[k] += e * l[k];
            ss += e;
        }
    }
    float iv = 1.f / (ss + 1e-16f);
    float v[8];
    {
        float4 ba = ((const float4*)bias)[2 * lane], bb = ((const float4*)bias)[2 * lane + 1];
        v[0] = acc[0] * iv + ba.x; v[1] = acc[1] * iv + ba.y;
        v[2] = acc[2] * iv + ba.z; v[3] = acc[3] * iv + ba.w;
        v[4] = acc[4] * iv + bb.x; v[5] = acc[5] * iv + bb.y;
        v[6] = acc[6] * iv + bb.z; v[7] = acc[7] * iv + bb.w;
    }
    if (res) {
        float4 ra = ((const float4*)(res + (size_t)d * DIM))[2 * lane];
        float4 rb = ((const float4*)(res + (size_t)d * DIM))[2 * lane + 1];
        v[0] += ra.x; v[1] += ra.y; v[2] += ra.z; v[3] += ra.w;
        v[4] += rb.x; v[5] += rb.y; v[6] += rb.z; v[7] += rb.w;
    }
    float sum = 0.f;
#pragma unroll
    for (int k = 0; k < 8; k++) sum += v[k];
    sum = warpReduceSum(sum);
    float mu = sum * (1.f / 256.f);
    float var = 0.f;
#pragma unroll
    for (int k = 0; k < 8; k++) { float dd = v[k] - mu; var += dd * dd; }
    var = warpReduceSum(var) * (1.f / 256.f);
    float inv = rsqrtf(var + 1e-5f);
    float4 ga = ((const float4*)lng)[2 * lane], gb = ((const float4*)lng)[2 * lane + 1];
    float4 ca4 = ((const float4*)lnb)[2 * lane], cb4 = ((const float4*)lnb)[2 * lane + 1];
    float o[8];
    o[0] = (v[0] - mu) * inv * ga.x + ca4.x; o[1] = (v[1] - mu) * inv * ga.y + ca4.y;
    o[2] = (v[2] - mu) * inv * ga.z + ca4.z; o[3] = (v[3] - mu) * inv * ga.w + ca4.w;
    o[4] = (v[4] - mu) * inv * gb.x + cb4.x; o[5] = (v[5] - mu) * inv * gb.y + cb4.y;
    o[6] = (v[6] - mu) * inv * gb.z + cb4.z; o[7] = (v[7] - mu) * inv * gb.w + cb4.w;
    if (out32) {
        float4* op = (float4*)(out32 + (size_t)d * DIM);
        op[2 * lane]     = make_float4(o[0], o[1], o[2], o[3]);
        op[2 * lane + 1] = make_float4(o[4], o[5], o[6], o[7]);
    }
    if (out16) {
        uint4 pk16;
        __half2 h0 = __floats2half2_rn(o[0], o[1]), h1 = __floats2half2_rn(o[2], o[3]);
        __half2 h2 = __floats2half2_rn(o[4], o[5]), h3 = __floats2half2_rn(o[6], o[7]);
        pk16.x = *(uint32_t*)&h0; pk16.y = *(uint32_t*)&h1;
        pk16.z = *(uint32_t*)&h2; pk16.w = *(uint32_t*)&h3;
        ((uint4*)(out16 + (size_t)d * DIM))[lane] = pk16;
    }
}

// ---------------- layernorm (dim=256); optional residual; fp32 + fp16 outputs ----------
__global__ void ln_kernel(const float* __restrict__ x, const float* __restrict__ res,
                          const float* __restrict__ g, const float* __restrict__ b,
                          float* __restrict__ out32, __half* __restrict__ out16, int n) {
    int row = blockIdx.x * 8 + (threadIdx.x >> 5);
    int lane = threadIdx.x & 31;
    if (row >= n) return;
    const float4* xr4 = (const float4*)(x + (size_t)row * DIM);
    const float4* rs4 = res ? (const float4*)(res + (size_t)row * DIM) : nullptr;
    float4 v[2];
    float sum = 0.f;
#pragma unroll
    for (int k = 0; k < 2; k++) {
        int q = k * 32 + lane;
        float4 t = xr4[q];
        if (rs4) { float4 r = rs4[q]; t.x += r.x; t.y += r.y; t.z += r.z; t.w += r.w; }
        v[k] = t;
        sum += t.x + t.y + t.z + t.w;
    }
    sum = warpReduceSum(sum);
    float mu = sum * (1.f / 256.f);
    float var = 0.f;
#pragma unroll
    for (int k = 0; k < 2; k++) {
        float dx = v[k].x - mu, dy = v[k].y - mu, dz = v[k].z - mu, dw = v[k].w - mu;
        var += dx * dx + dy * dy + dz * dz + dw * dw;
    }
    var = warpReduceSum(var) * (1.f / 256.f);
    float inv = rsqrtf(var + 1e-5f);
    const float4* g4 = (const float4*)g;
    const float4* b4 = (const float4*)b;
#pragma unroll
    for (int k = 0; k < 2; k++) {
        int q = k * 32 + lane;
        float4 gg = g4[q], bb = b4[q];
        float4 o = make_float4((v[k].x - mu) * inv * gg.x + bb.x,
                               (v[k].y - mu) * inv * gg.y + bb.y,
                               (v[k].z - mu) * inv * gg.z + bb.z,
                               (v[k].w - mu) * inv * gg.w + bb.w);
        if (out32) ((float4*)(out32 + (size_t)row * DIM))[q] = o;
        if (out16) {
            __half2* o16 = (__half2*)(out16 + (size_t)row * DIM);
            o16[q * 2]     = __floats2half2_rn(o.x, o.y);
            o16[q * 2 + 1] = __floats2half2_rn(o.z, o.w);
        }
    }
}

// ---------------- host ----------------
#define DYN_SMEM (4 * CHUNK_WORDS * sizeof(uint32_t))   // 73728 bytes

static inline void launch_tgemm32(const __half* A, const __half* WT, const float* bias,
                                  float* C, int M, int N, int K) {
    dim3 grid((N + 127) / 128, (M + 127) / 128);
    mma_gemm_h<<<grid, 256, DYN_SMEM>>>(A, WT, bias, C, nullptr, M, N, K);
}
static inline void launch_tgemm16(const __half* A, const __half* WT, __half* C,
                                  int M, int N, int K) {
    dim3 grid((N + 127) / 128, (M + 127) / 128);
    mma_gemm_h<<<grid, 256, DYN_SMEM>>>(A, WT, nullptr, nullptr, C, M, N, K);
}

extern "C" void kernel_launch(void* const* d_in, const int* in_sizes, int n_in,
                              void* d_out, int out_size) {
    cudaFuncSetAttribute(mma_gemm_h, cudaFuncAttributeMaxDynamicSharedMemorySize, DYN_SMEM);

    const float* x_gnn = (const float*)d_in[0];
    const int*   eidx  = (const int*)d_in[1];
    const float* eattr = (const float*)d_in[2];
    const float* W_in  = (const float*)d_in[3];
    const float* b_in  = (const float*)d_in[4];
    const float* Wl1   = (const float*)d_in[5];
    const float* Wr1   = (const float*)d_in[6];
    const float* We1   = (const float*)d_in[7];
    const float* att1  = (const float*)d_in[8];
    const float* bg1   = (const float*)d_in[9];
    const float* ln1_g = (const float*)d_in[10];
    const float* ln1_b = (const float*)d_in[11];
    const float* W_down= (const float*)d_in[12];
    const float* lnd_g = (const float*)d_in[13];
    const float* lnd_b = (const float*)d_in[14];
    const float* Wl2   = (const float*)d_in[15];
    const float* Wr2   = (const float*)d_in[16];
    const float* We2   = (const float*)d_in[17];
    const float* att2  = (const float*)d_in[18];
    const float* bg2   = (const float*)d_in[19];
    const float* ln2_g = (const float*)d_in[20];
    const float* ln2_b = (const float*)d_in[21];
    const float* W_up  = (const float*)d_in[22];
    const float* lnu_g = (const float*)d_in[23];
    const float* lnu_b = (const float*)d_in[24];
    const float* W_cls = (const float*)d_in[25];
    const float* b_cls = (const float*)d_in[26];

    const int n = in_sizes[0] / 18;        // 20000
    const int E = in_sizes[1] / 2;         // 320000
    const int* src = eidx;
    const int* dst = eidx + E;

    float *h1, *z, *tmp;
    __half *xlr, *h0h, *h1h, *zh, *z2h, *outh, *wth;
    int *deg, *cur, *off, *bsum, *syn;
    int2 *epack;
    cudaGetSymbolAddress((void**)&xlr, g_xlr);
    cudaGetSymbolAddress((void**)&h1, g_h1);
    cudaGetSymbolAddress((void**)&z, g_z);
    cudaGetSymbolAddress((void**)&tmp, g_tmp);
    cudaGetSymbolAddress((void**)&h0h, g_h0h);
    cudaGetSymbolAddress((void**)&h1h, g_h1h);
    cudaGetSymbolAddress((void**)&zh, g_zh);
    cudaGetSymbolAddress((void**)&z2h, g_z2h);
    cudaGetSymbolAddress((void**)&outh, g_outh);
    cudaGetSymbolAddress((void**)&wth, g_wth);
    cudaGetSymbolAddress((void**)&deg, g_deg);
    cudaGetSymbolAddress((void**)&cur, g_cur);
    cudaGetSymbolAddress((void**)&off, g_off);
    cudaGetSymbolAddress((void**)&bsum, g_bsum);
    cudaGetSymbolAddress((void**)&syn, g_sync);
    cudaGetSymbolAddress((void**)&epack, g_epack);

    float* out_logits = (float*)d_out;
    float* out_h = (float*)d_out + (size_t)n * 1000;

    const int lnBlocks = (n + 7) / 8;
    const int nodeBlocks = (n + 7) / 8;
    const int scanBlocks = (n + SCAN_CHUNK - 1) / SCAN_CHUNK;   // 10
    const int histBlocks = (E + 255) / 256;                     // 1250

    // ---- fused prologue ----
    {
        PrologueArgs pa;
        auto set = [&](int i, const float* in, __half* out, int Kreal, int Kpad, int N, int& cum) {
            pa.d[i].in = in; pa.d[i].out = out;
            pa.d[i].Kreal = Kreal; pa.d[i].Kpad = Kpad; pa.d[i].N = N;
            pa.d[i].blkStart = cum; pa.d[i].nx = (N + 31) / 32;
            cum += pa.d[i].nx * ((Kpad + 31) / 32);
        };
        int cum = 0;
        set(0, Wl1,    wth + WTH_L1,            32, 64, DIM, cum);
        set(1, Wr1,    wth + WTH_L1 + 256 * 64, 32, 64, DIM, cum);
        set(2, W_down, wth + WTH_DN,  DIM, DIM, DIM, cum);
        set(3, Wl2,    wth + WTH_L2,  DIM, DIM, DIM, cum);
        set(4, Wr2,    wth + WTH_L2 + 256 * 256, DIM, DIM, DIM, cum);
        set(5, W_up,   wth + WTH_UP,  DIM, DIM, DIM, cum);
        set(6, W_cls,  wth + WTH_CLS, DIM, DIM, 1000, cum);
        pa.tcum = cum;
        pa.zb = (2 * n + 255) / 256;
        pa.deg = deg; pa.cur = cur; pa.sync = syn;
        pa.x = x_gnn; pa.W_in = W_in; pa.b_in = b_in; pa.h0h = h0h;
        pa.n = n;
        int total = pa.zb + cum + (n + 7) / 8;
        prologue_kernel<<<total, 256>>>(pa);
    }

    // ---- GAT layer 1 GEMM (independent of CSR) ----
    launch_tgemm16(h0h, wth + WTH_L1, xlr, n, 512, 64);

    // ---- fused CSR build + scatter ----
    csr_build_kernel<<<histBlocks + scanBlocks, 256>>>(dst, deg, off, bsum, syn,
                                                       histBlocks, n, E);
    scatter_kernel<<<(E + 1023) / 1024, 256>>>(src, dst, eattr, off, cur, epack, E);

    // ---- GAT layer 1 gather+LN ----
    gatln_kernel<<<nodeBlocks, 256>>>(xlr, off, epack, We1, att1, bg1,
                                      nullptr, ln1_g, ln1_b, h1, h1h, n);

    // ---- bottleneck down ----
    launch_tgemm32(h1h, wth + WTH_DN, nullptr, tmp, n, DIM, DIM);
    ln_kernel<<<lnBlocks, 256>>>(tmp, nullptr, lnd_g, lnd_b, z, zh, n);

    // ---- GAT layer 2 (residual z inside fused gather-LN) ----
    launch_tgemm16(zh, wth + WTH_L2, xlr, n, 512, DIM);
    gatln_kernel<<<nodeBlocks, 256>>>(xlr, off, epack, We2, att2, bg2,
                                      z, ln2_g, ln2_b, nullptr, z2h, n);

    // ---- up projection + final LN ----
    launch_tgemm32(z2h, wth + WTH_UP, nullptr, tmp, n, DIM, DIM);
    ln_kernel<<<lnBlocks, 256>>>(tmp, h1, lnu_g, lnu_b, out_h, outh, n);

    // ---- classifier ----
    launch_tgemm32(outh, wth + WTH_CLS, b_cls, out_logits, n, 1000, DIM);
}

// round 15
// speedup vs baseline: 1.0414x; 1.0414x over previous
#include <cuda_runtime.h>
#include <cuda_fp16.h>
#include <math.h>
#include <stdint.h>

// ---------------- problem constants ----------------
#define NMAX 20000
#define EMAX 320000
#define DIM 256
#define HEADS 8

// ---------------- scratch ----------------
__device__ __align__(16) __half g_xlr[NMAX * 512];      // fp16: [n,0:256]=xl, [n,256:512]=xr
__device__ __align__(16) float g_h1[NMAX * DIM];
__device__ __align__(16) float g_z[NMAX * DIM];
__device__ __align__(16) float g_tmp[NMAX * DIM];
// fp16 activation copies (GEMM A operands)
__device__ __align__(16) __half g_h0h[NMAX * 64];
__device__ __align__(16) __half g_h1h[NMAX * DIM];
__device__ __align__(16) __half g_zh[NMAX * DIM];
__device__ __align__(16) __half g_z2h[NMAX * DIM];
__device__ __align__(16) __half g_outh[NMAX * DIM];
// CSR by dst
__device__ int   g_deg[NMAX];
__device__ int   g_cur[NMAX];              // running cursor, initialized to off[] by csr_build
__device__ int   g_off[NMAX + 1];
__device__ int   g_bsum[32];
__device__ int   g_sync[40];               // [0]=hist done counter, [1..32]=chunk flags
__device__ int2  g_epack[EMAX];            // .x = src, .y = float bits of edge_attr
// fp16 transposed weights
#define WTH_L1  0
#define WTH_DN  32768
#define WTH_L2  98304
#define WTH_UP  229376
#define WTH_CLS 294912
#define WTH_TOTAL (294912 + 256000)
__device__ __align__(16) __half g_wth[WTH_TOTAL];

#define SCAN_CHUNK 2048

// ---------------- helpers ----------------
__device__ __forceinline__ float warpReduceSum(float v) {
#pragma unroll
    for (int o = 16; o > 0; o >>= 1) v += __shfl_xor_sync(0xffffffffu, v, o);
    return v;
}

__device__ __forceinline__ float leaky(float v) { return v > 0.f ? v : 0.2f * v; }

__device__ __forceinline__ uint32_t smem_u32(const void* p) {
    uint32_t a;
    asm("{ .reg .u64 t; cvta.to.shared.u64 t, %1; cvt.u32.u64 %0, t; }" : "=r"(a) : "l"(p));
    return a;
}

__device__ __forceinline__ void cpasync16(uint32_t dst, const void* src, bool valid) {
    int sz = valid ? 16 : 0;
    asm volatile("cp.async.cg.shared.global [%0], [%1], 16, %2;"
                 :: "r"(dst), "l"(src), "r"(sz));
}
__device__ __forceinline__ void cpasync_commit() { asm volatile("cp.async.commit_group;"); }
__device__ __forceinline__ void cpasync_wait0() { asm volatile("cp.async.wait_group 0;"); }

#define LDMATRIX_X4(r0, r1, r2, r3, addr) \
    asm volatile("ldmatrix.sync.aligned.m8n8.x4.shared.b16 {%0,%1,%2,%3}, [%4];" \
                 : "=r"(r0), "=r"(r1), "=r"(r2), "=r"(r3) : "r"(addr))

__device__ __forceinline__ int ldcg_i(const int* p) {
    int v;
    asm volatile("ld.global.cg.b32 %0, [%1];" : "=r"(v) : "l"(p));
    return v;
}

// ---------------- fused prologue: zero(deg,sync) + transpose-all + inproj --------------
struct TransDesc { const float* in; __half* out; int Kreal, Kpad, N, blkStart, nx; };
struct PrologueArgs {
    TransDesc d[7];
    int tcum;
    int zb;
    int* deg; int* sync;
    const float* x; const float* W_in; const float* b_in; __half* h0h;
    int n;
};

__global__ void prologue_kernel(PrologueArgs pa) {
    __shared__ float sbuf[32 * 33];
    int bid = blockIdx.x;
    int tid = threadIdx.x;
    if (bid < pa.zb) {
        int i = bid * 256 + tid;
        if (i < pa.n) pa.deg[i] = 0;
        if (bid == 0 && tid < 40) pa.sync[tid] = 0;
        return;
    }
    bid -= pa.zb;
    if (bid < pa.tcum) {
        float (*t)[33] = (float(*)[33])sbuf;
        int di = 0;
#pragma unroll
        for (int i = 1; i < 7; i++) if (bid >= pa.d[i].blkStart) di = i;
        const TransDesc& D = pa.d[di];
        int rem = bid - D.blkStart;
        int bx = (rem % D.nx) * 32, by = (rem / D.nx) * 32;
        int tx = tid & 31, ty = tid >> 5;
        int x = bx + tx, y = by + ty;
#pragma unroll
        for (int i = 0; i < 32; i += 8)
            t[ty + i][tx] = (x < D.N && y + i < D.Kreal) ? D.in[(size_t)(y + i) * D.N + x] : 0.f;
        __syncthreads();
        x = by + tx;
        y = bx + ty;
#pragma unroll
        for (int i = 0; i < 32; i += 8)
            if (x < D.Kpad && y + i < D.N)
                D.out[(size_t)(y + i) * D.Kpad + x] = __float2half(t[tx][ty + i]);
        return;
    }
    bid -= pa.tcum;
    {
        float* sW = sbuf;
        float* sb = sbuf + 576;
        for (int i = tid; i < 18 * 32; i += 256) sW[i] = pa.W_in[i];
        if (tid < 32) sb[tid] = pa.b_in[tid];
        __syncthreads();
        int row = bid * 8 + (tid >> 5);
        int col = tid & 31;
        if (row >= pa.n) return;
        const float* xr = pa.x + (size_t)row * 18;
        float v = sb[col];
#pragma unroll
        for (int k = 0; k < 18; k++) v += xr[k] * sW[k * 32 + col];
        pa.h0h[(size_t)row * 64 + col] = __float2half(v);
        pa.h0h[(size_t)row * 64 + 32 + col] = __float2half(0.f);
    }
}

// ---------------- fused CSR build: hist + two-level scan; also seeds cur = off ---------
__global__ void csr_build_kernel(const int* __restrict__ dst, int* __restrict__ deg,
                                 int* __restrict__ off, int* __restrict__ cur,
                                 int* __restrict__ bsum, int* __restrict__ syn,
                                 int HB, int n, int E) {
    int bid = blockIdx.x;
    int tid = threadIdx.x;
    if (bid < HB) {
        int e = bid * 256 + tid;
        if (e < E) atomicAdd(&deg[dst[e]], 1);
        __threadfence();
        __syncthreads();
        if (tid == 0) atomicAdd(&syn[0], 1);
        return;
    }
    int b = bid - HB;
    if (tid == 0) { while (atomicAdd(&syn[0], 0) < HB) { } }
    __syncthreads();
    __shared__ int wsum[8];
    __shared__ int pre_s;
    int base = b * SCAN_CHUNK + tid * 8;
    int e8[8];
    int s = 0;
#pragma unroll
    for (int k = 0; k < 8; k++) {
        int i = base + k;
        int v = (i < n) ? ldcg_i(&deg[i]) : 0;
        e8[k] = s;
        s += v;
    }
    int x = s;
#pragma unroll
    for (int o = 1; o < 32; o <<= 1) {
        int y = __shfl_up_sync(0xffffffffu, x, o);
        if ((tid & 31) >= o) x += y;
    }
    if ((tid & 31) == 31) wsum[tid >> 5] = x;
    __syncthreads();
    if (tid < 8) {
        int t = wsum[tid];
#pragma unroll
        for (int o = 1; o < 8; o <<= 1) {
            int y = __shfl_up_sync(0xffu, t, o);
            if (tid >= o) t += y;
        }
        wsum[tid] = t;
    }
    __syncthreads();
    int thrOff = (x - s) + ((tid >= 32) ? wsum[(tid >> 5) - 1] : 0);
    if (tid == 255) {
        bsum[b] = thrOff + s;
        __threadfence();
        atomicExch(&syn[1 + b], 1);
    }
    if (tid < 32) {
        int v = 0;
        if (tid < b) {
            while (atomicAdd(&syn[1 + tid], 0) == 0) { }
            v = atomicAdd(&bsum[tid], 0);
        }
#pragma unroll
        for (int o = 16; o > 0; o >>= 1) v += __shfl_xor_sync(0xffffffffu, v, o);
        if (tid == 0) pre_s = v;
    }
    __syncthreads();
    int pre = pre_s;
#pragma unroll
    for (int k = 0; k < 8; k++) {
        int i = base + k;
        if (i < n) {
            int o = pre + thrOff + e8[k];
            off[i] = o;
            cur[i] = o;               // seed running cursor
        }
    }
    if (b == 0 && tid == 0) off[n] = E;
}

// ---------------- scatter: one edge/thread; cur doubles as cursor (no off load) --------
__global__ void scatter_kernel(const int* __restrict__ src, const int* __restrict__ dst,
                               const float* __restrict__ ea,
                               int* __restrict__ cur, int2* __restrict__ epack, int E) {
    int e = blockIdx.x * blockDim.x + threadIdx.x;
    if (e >= E) return;
    int d = dst[e];
    int pos = atomicAdd(&cur[d], 1);
    epack[pos] = make_int2(src[e], __float_as_int(ea[e]));
}

// ---------------- fp16 mma.sync GEMM: out = A[M,K] @ WT[N,K]^T (+bias), fp32 accum ------
#define SWW 36
#define CHUNK_WORDS (128 * SWW)

extern __shared__ uint32_t g_dynsmem_u[];

__global__ __launch_bounds__(256)
void mma_gemm_h(const __half* __restrict__ A, const __half* __restrict__ WT,
                const float* __restrict__ bias, float* __restrict__ C32,
                __half* __restrict__ C16, int M, int N, int K) {
    const int tid = threadIdx.x;
    const int wid = tid >> 5, lane = tid & 31;
    const int gid = lane >> 2, tig = lane & 3;
    const int wm = (wid >> 2) * 64, wn = (wid & 3) * 32;
    const int m0 = blockIdx.y * 128, n0 = blockIdx.x * 128;

    float acc[4][4][4];
#pragma unroll
    for (int mi = 0; mi < 4; mi++)
#pragma unroll
        for (int ni = 0; ni < 4; ni++)
#pragma unroll
            for (int q = 0; q < 4; q++) acc[mi][ni][q] = 0.f;

    const int nc = (K + 63) >> 6;
    uint32_t aAddr[2], bAddr[2];
    aAddr[0] = smem_u32(g_dynsmem_u);
    bAddr[0] = aAddr[0] + CHUNK_WORDS * 4;
    aAddr[1] = aAddr[0] + 2 * CHUNK_WORDS * 4;
    bAddr[1] = aAddr[0] + 3 * CHUNK_WORDS * 4;

    const uint32_t aOff = (uint32_t)((wm + (lane & 15)) * 144 + (lane >> 4) * 16);
    const uint32_t bOff = (uint32_t)((wn + (lane & 7) + ((lane >> 4) << 3)) * 144
                                     + ((lane >> 3) & 1) * 16);

    auto issue = [&](int c, int b) {
        int k0 = c << 6;
        int Kc = K - k0; if (Kc > 64) Kc = 64;
#pragma unroll
        for (int i = 0; i < 4; i++) {
            int idx = tid + i * 256;
            int row = idx >> 3, q = idx & 7;
            uint32_t soff = (uint32_t)(row * 144 + q * 16);
            bool kv = (q * 8) < Kc;
            cpasync16(aAddr[b] + soff, A + (size_t)(m0 + row) * K + k0 + q * 8,
                      kv && (m0 + row < M));
            cpasync16(bAddr[b] + soff, WT + (size_t)(n0 + row) * K + k0 + q * 8,
                      kv && (n0 + row < N));
        }
        cpasync_commit();
    };

    issue(0, 0);
    for (int c = 0; c < nc; c++) {
        int cur = c & 1;
        cpasync_wait0();
        __syncthreads();
        if (c + 1 < nc) issue(c + 1, cur ^ 1);
        uint32_t aB = aAddr[cur] + aOff;
        uint32_t bB = bAddr[cur] + bOff;
        int Kc = K - (c << 6); if (Kc > 64) Kc = 64;
#pragma unroll
        for (int ks = 0; ks < 4; ks++) {
            if (ks * 16 < Kc) {
                uint32_t af[4][4], bf[4][2];
#pragma unroll
                for (int mi = 0; mi < 4; mi++)
                    LDMATRIX_X4(af[mi][0], af[mi][1], af[mi][2], af[mi][3],
                                aB + mi * 16 * 144 + ks * 32);
#pragma unroll
                for (int np = 0; np < 2; np++)
                    LDMATRIX_X4(bf[2 * np][0], bf[2 * np][1], bf[2 * np + 1][0], bf[2 * np + 1][1],
                                bB + np * 16 * 144 + ks * 32);
#pragma unroll
                for (int mi = 0; mi < 4; mi++)
#pragma unroll
                    for (int ni = 0; ni < 4; ni++) {
                        asm volatile(
                            "mma.sync.aligned.m16n8k16.row.col.f32.f16.f16.f32 "
                            "{%0,%1,%2,%3}, {%4,%5,%6,%7}, {%8,%9}, {%0,%1,%2,%3};"
                            : "+f"(acc[mi][ni][0]), "+f"(acc[mi][ni][1]),
                              "+f"(acc[mi][ni][2]), "+f"(acc[mi][ni][3])
                            : "r"(af[mi][0]), "r"(af[mi][1]), "r"(af[mi][2]), "r"(af[mi][3]),
                              "r"(bf[ni][0]), "r"(bf[ni][1]));
                    }
            }
        }
    }

#pragma unroll
    for (int mi = 0; mi < 4; mi++) {
        int r0 = m0 + wm + mi * 16 + gid;
        int r1 = r0 + 8;
#pragma unroll
        for (int ni = 0; ni < 4; ni++) {
            int col = n0 + wn + ni * 8 + tig * 2;
            if (col >= N) continue;
            if (C16) {
                if (r0 < M)
                    *(__half2*)(C16 + (size_t)r0 * N + col) =
                        __floats2half2_rn(acc[mi][ni][0], acc[mi][ni][1]);
                if (r1 < M)
                    *(__half2*)(C16 + (size_t)r1 * N + col) =
                        __floats2half2_rn(acc[mi][ni][2], acc[mi][ni][3]);
            } else {
                float bx = 0.f, by = 0.f;
                if (bias) { bx = bias[col]; by = bias[col + 1]; }
                if (r0 < M)
                    *(float2*)(C32 + (size_t)r0 * N + col) =
                        make_float2(acc[mi][ni][0] + bx, acc[mi][ni][1] + by);
                if (r1 < M)
                    *(float2*)(C32 + (size_t)r1 * N + col) =
                        make_float2(acc[mi][ni][2] + bx, acc[mi][ni][3] + by);
            }
        }
    }
}

// ---------------- fused CSR gather GAT + LayerNorm (fp16 xlr), prefetch depth 1 ---------
__global__ void gatln_kernel(const __half* __restrict__ xlr,
                             const int* __restrict__ off, const int2* __restrict__ epack,
                             const float* __restrict__ We, const float* __restrict__ att,
                             const float* __restrict__ bias, const float* __restrict__ res,
                             const float* __restrict__ lng, const float* __restrict__ lnb,
                             float* __restrict__ out32, __half* __restrict__ out16, int n) {
    int d = (blockIdx.x * blockDim.x + threadIdx.x) >> 5;
    int lane = threadIdx.x & 31;
    if (d >= n) return;
    float r[8], w[8], t[8];
    {
        uint4 rv = ((const uint4*)(xlr + (size_t)d * 512 + 256))[lane];
        const __half2* hp = (const __half2*)&rv;
#pragma unroll
        for (int k = 0; k < 4; k++) {
            float2 f = __half22float2(hp[k]);
            r[2 * k] = f.x; r[2 * k + 1] = f.y;
        }
        float4 wa = ((const float4*)We)[2 * lane], wb = ((const float4*)We)[2 * lane + 1];
        w[0] = wa.x; w[1] = wa.y; w[2] = wa.z; w[3] = wa.w;
        w[4] = wb.x; w[5] = wb.y; w[6] = wb.z; w[7] = wb.w;
        float4 ta = ((const float4*)att)[2 * lane], tb = ((const float4*)att)[2 * lane + 1];
        t[0] = ta.x; t[1] = ta.y; t[2] = ta.z; t[3] = ta.w;
        t[4] = tb.x; t[5] = tb.y; t[6] = tb.z; t[7] = tb.w;
    }
    float acc[8];
#pragma unroll
    for (int k = 0; k < 8; k++) acc[k] = 0.f;
    float ss = 0.f;
    int beg = off[d], cnt = off[d + 1] - beg;
    const int2* ep = epack + beg;
    if (cnt > 0) {
        int2 pk = ep[0];
        uint4 lv = ((const uint4*)(xlr + (size_t)pk.x * 512))[lane];
        float aa = __int_as_float(pk.y);
        for (int i = 0; i < cnt; i++) {
            uint4 cv = lv;
            float ca = aa;
            if (i + 1 < cnt) {
                int2 p2 = ep[i + 1];
                lv = ((const uint4*)(xlr + (size_t)p2.x * 512))[lane];
                aa = __int_as_float(p2.y);
            }
            float l[8];
            const __half2* hp = (const __half2*)&cv;
#pragma unroll
            for (int k = 0; k < 4; k++) {
                float2 f = __half22float2(hp[k]);
                l[2 * k] = f.x; l[2 * k + 1] = f.y;
            }
            float p = 0.f;
#pragma unroll
            for (int k = 0; k < 8; k++) p += leaky(l[k] + r[k] + ca * w[k]) * t[k];
            p += __shfl_xor_sync(0xffffffffu, p, 1);
            p += __shfl_xor_sync(0xffffffffu, p, 2);
            float e = __expf(p);
#pragma unroll
            for (int k = 0; k < 8; k++) acc[k] += e * l[k];
            ss += e;
        }
    }
    float iv = 1.f / (ss + 1e-16f);
    float v[8];
    {
        float4 ba = ((const float4*)bias)[2 * lane], bb = ((const float4*)bias)[2 * lane + 1];
        v[0] = acc[0] * iv + ba.x; v[1] = acc[1] * iv + ba.y;
        v[2] = acc[2] * iv + ba.z; v[3] = acc[3] * iv + ba.w;
        v[4] = acc[4] * iv + bb.x; v[5] = acc[5] * iv + bb.y;
        v[6] = acc[6] * iv + bb.z; v[7] = acc[7] * iv + bb.w;
    }
    if (res) {
        float4 ra = ((const float4*)(res + (size_t)d * DIM))[2 * lane];
        float4 rb = ((const float4*)(res + (size_t)d * DIM))[2 * lane + 1];
        v[0] += ra.x; v[1] += ra.y; v[2] += ra.z; v[3] += ra.w;
        v[4] += rb.x; v[5] += rb.y; v[6] += rb.z; v[7] += rb.w;
    }
    float sum = 0.f;
#pragma unroll
    for (int k = 0; k < 8; k++) sum += v[k];
    sum = warpReduceSum(sum);
    float mu = sum * (1.f / 256.f);
    float var = 0.f;
#pragma unroll
    for (int k = 0; k < 8; k++) { float dd = v[k] - mu; var += dd * dd; }
    var = warpReduceSum(var) * (1.f / 256.f);
    float inv = rsqrtf(var + 1e-5f);
    float4 ga = ((const float4*)lng)[2 * lane], gb = ((const float4*)lng)[2 * lane + 1];
    float4 ca4 = ((const float4*)lnb)[2 * lane], cb4 = ((const float4*)lnb)[2 * lane + 1];
    float o[8];
    o[0] = (v[0] - mu) * inv * ga.x + ca4.x; o[1] = (v[1] - mu) * inv * ga.y + ca4.y;
    o[2] = (v[2] - mu) * inv * ga.z + ca4.z; o[3] = (v[3] - mu) * inv * ga.w + ca4.w;
    o[4] = (v[4] - mu) * inv * gb.x + cb4.x; o[5] = (v[5] - mu) * inv * gb.y + cb4.y;
    o[6] = (v[6] - mu) * inv * gb.z + cb4.z; o[7] = (v[7] - mu) * inv * gb.w + cb4.w;
    if (out32) {
        float4* op = (float4*)(out32 + (size_t)d * DIM);
        op[2 * lane]     = make_float4(o[0], o[1], o[2], o[3]);
        op[2 * lane + 1] = make_float4(o[4], o[5], o[6], o[7]);
    }
    if (out16) {
        uint4 pk16;
        __half2 h0 = __floats2half2_rn(o[0], o[1]), h1 = __floats2half2_rn(o[2], o[3]);
        __half2 h2 = __floats2half2_rn(o[4], o[5]), h3 = __floats2half2_rn(o[6], o[7]);
        pk16.x = *(uint32_t*)&h0; pk16.y = *(uint32_t*)&h1;
        pk16.z = *(uint32_t*)&h2; pk16.w = *(uint32_t*)&h3;
        ((uint4*)(out16 + (size_t)d * DIM))[lane] = pk16;
    }
}

// ---------------- layernorm (dim=256); optional residual; fp32 + fp16 outputs ----------
__global__ void ln_kernel(const float* __restrict__ x, const float* __restrict__ res,
                          const float* __restrict__ g, const float* __restrict__ b,
                          float* __restrict__ out32, __half* __restrict__ out16, int n) {
    int row = blockIdx.x * 8 + (threadIdx.x >> 5);
    int lane = threadIdx.x & 31;
    if (row >= n) return;
    const float4* xr4 = (const float4*)(x + (size_t)row * DIM);
    const float4* rs4 = res ? (const float4*)(res + (size_t)row * DIM) : nullptr;
    float4 v[2];
    float sum = 0.f;
#pragma unroll
    for (int k = 0; k < 2; k++) {
        int q = k * 32 + lane;
        float4 t = xr4[q];
        if (rs4) { float4 r = rs4[q]; t.x += r.x; t.y += r.y; t.z += r.z; t.w += r.w; }
        v[k] = t;
        sum += t.x + t.y + t.z + t.w;
    }
    sum = warpReduceSum(sum);
    float mu = sum * (1.f / 256.f);
    float var = 0.f;
#pragma unroll
    for (int k = 0; k < 2; k++) {
        float dx = v[k].x - mu, dy = v[k].y - mu, dz = v[k].z - mu, dw = v[k].w - mu;
        var += dx * dx + dy * dy + dz * dz + dw * dw;
    }
    var = warpReduceSum(var) * (1.f / 256.f);
    float inv = rsqrtf(var + 1e-5f);
    const float4* g4 = (const float4*)g;
    const float4* b4 = (const float4*)b;
#pragma unroll
    for (int k = 0; k < 2; k++) {
        int q = k * 32 + lane;
        float4 gg = g4[q], bb = b4[q];
        float4 o = make_float4((v[k].x - mu) * inv * gg.x + bb.x,
                               (v[k].y - mu) * inv * gg.y + bb.y,
                               (v[k].z - mu) * inv * gg.z + bb.z,
                               (v[k].w - mu) * inv * gg.w + bb.w);
        if (out32) ((float4*)(out32 + (size_t)row * DIM))[q] = o;
        if (out16) {
            __half2* o16 = (__half2*)(out16 + (size_t)row * DIM);
            o16[q * 2]     = __floats2half2_rn(o.x, o.y);
            o16[q * 2 + 1] = __floats2half2_rn(o.z, o.w);
        }
    }
}

// ---------------- host ----------------
#define DYN_SMEM (4 * CHUNK_WORDS * sizeof(uint32_t))   // 73728 bytes

static inline void launch_tgemm32(const __half* A, const __half* WT, const float* bias,
                                  float* C, int M, int N, int K) {
    dim3 grid((N + 127) / 128, (M + 127) / 128);
    mma_gemm_h<<<grid, 256, DYN_SMEM>>>(A, WT, bias, C, nullptr, M, N, K);
}
static inline void launch_tgemm16(const __half* A, const __half* WT, __half* C,
                                  int M, int N, int K) {
    dim3 grid((N + 127) / 128, (M + 127) / 128);
    mma_gemm_h<<<grid, 256, DYN_SMEM>>>(A, WT, nullptr, nullptr, C, M, N, K);
}

extern "C" void kernel_launch(void* const* d_in, const int* in_sizes, int n_in,
                              void* d_out, int out_size) {
    cudaFuncSetAttribute(mma_gemm_h, cudaFuncAttributeMaxDynamicSharedMemorySize, DYN_SMEM);

    const float* x_gnn = (const float*)d_in[0];
    const int*   eidx  = (const int*)d_in[1];
    const float* eattr = (const float*)d_in[2];
    const float* W_in  = (const float*)d_in[3];
    const float* b_in  = (const float*)d_in[4];
    const float* Wl1   = (const float*)d_in[5];
    const float* Wr1   = (const float*)d_in[6];
    const float* We1   = (const float*)d_in[7];
    const float* att1  = (const float*)d_in[8];
    const float* bg1   = (const float*)d_in[9];
    const float* ln1_g = (const float*)d_in[10];
    const float* ln1_b = (const float*)d_in[11];
    const float* W_down= (const float*)d_in[12];
    const float* lnd_g = (const float*)d_in[13];
    const float* lnd_b = (const float*)d_in[14];
    const float* Wl2   = (const float*)d_in[15];
    const float* Wr2   = (const float*)d_in[16];
    const float* We2   = (const float*)d_in[17];
    const float* att2  = (const float*)d_in[18];
    const float* bg2   = (const float*)d_in[19];
    const float* ln2_g = (const float*)d_in[20];
    const float* ln2_b = (const float*)d_in[21];
    const float* W_up  = (const float*)d_in[22];
    const float* lnu_g = (const float*)d_in[23];
    const float* lnu_b = (const float*)d_in[24];
    const float* W_cls = (const float*)d_in[25];
    const float* b_cls = (const float*)d_in[26];

    const int n = in_sizes[0] / 18;        // 20000
    const int E = in_sizes[1] / 2;         // 320000
    const int* src = eidx;
    const int* dst = eidx + E;

    float *h1, *z, *tmp;
    __half *xlr, *h0h, *h1h, *zh, *z2h, *outh, *wth;
    int *deg, *cur, *off, *bsum, *syn;
    int2 *epack;
    cudaGetSymbolAddress((void**)&xlr, g_xlr);
    cudaGetSymbolAddress((void**)&h1, g_h1);
    cudaGetSymbolAddress((void**)&z, g_z);
    cudaGetSymbolAddress((void**)&tmp, g_tmp);
    cudaGetSymbolAddress((void**)&h0h, g_h0h);
    cudaGetSymbolAddress((void**)&h1h, g_h1h);
    cudaGetSymbolAddress((void**)&zh, g_zh);
    cudaGetSymbolAddress((void**)&z2h, g_z2h);
    cudaGetSymbolAddress((void**)&outh, g_outh);
    cudaGetSymbolAddress((void**)&wth, g_wth);
    cudaGetSymbolAddress((void**)&deg, g_deg);
    cudaGetSymbolAddress((void**)&cur, g_cur);
    cudaGetSymbolAddress((void**)&off, g_off);
    cudaGetSymbolAddress((void**)&bsum, g_bsum);
    cudaGetSymbolAddress((void**)&syn, g_sync);
    cudaGetSymbolAddress((void**)&epack, g_epack);

    float* out_logits = (float*)d_out;
    float* out_h = (float*)d_out + (size_t)n * 1000;

    const int lnBlocks = (n + 7) / 8;
    const int nodeBlocks = (n + 7) / 8;
    const int scanBlocks = (n + SCAN_CHUNK - 1) / SCAN_CHUNK;   // 10
    const int histBlocks = (E + 255) / 256;                     // 1250

    // ---- fused prologue: zero(deg,sync) + weight transposes + input projection ----
    {
        PrologueArgs pa;
        auto set = [&](int i, const float* in, __half* out, int Kreal, int Kpad, int N, int& cum) {
            pa.d[i].in = in; pa.d[i].out = out;
            pa.d[i].Kreal = Kreal; pa.d[i].Kpad = Kpad; pa.d[i].N = N;
            pa.d[i].blkStart = cum; pa.d[i].nx = (N + 31) / 32;
            cum += pa.d[i].nx * ((Kpad + 31) / 32);
        };
        int cum = 0;
        set(0, Wl1,    wth + WTH_L1,            32, 64, DIM, cum);
        set(1, Wr1,    wth + WTH_L1 + 256 * 64, 32, 64, DIM, cum);
        set(2, W_down, wth + WTH_DN,  DIM, DIM, DIM, cum);
        set(3, Wl2,    wth + WTH_L2,  DIM, DIM, DIM, cum);
        set(4, Wr2,    wth + WTH_L2 + 256 * 256, DIM, DIM, DIM, cum);
        set(5, W_up,   wth + WTH_UP,  DIM, DIM, DIM, cum);
        set(6, W_cls,  wth + WTH_CLS, DIM, DIM, 1000, cum);
        pa.tcum = cum;
        pa.zb = (n + 255) / 256;
        pa.deg = deg; pa.sync = syn;
        pa.x = x_gnn; pa.W_in = W_in; pa.b_in = b_in; pa.h0h = h0h;
        pa.n = n;
        int total = pa.zb + cum + (n + 7) / 8;
        prologue_kernel<<<total, 256>>>(pa);
    }

    // ---- GAT layer 1 GEMM (independent of CSR) ----
    launch_tgemm16(h0h, wth + WTH_L1, xlr, n, 512, 64);

    // ---- fused CSR build (seeds cur=off) + scatter ----
    csr_build_kernel<<<histBlocks + scanBlocks, 256>>>(dst, deg, off, cur, bsum, syn,
                                                       histBlocks, n, E);
    scatter_kernel<<<histBlocks, 256>>>(src, dst, eattr, cur, epack, E);

    // ---- GAT layer 1 gather+LN ----
    gatln_kernel<<<nodeBlocks, 256>>>(xlr, off, epack, We1, att1, bg1,
                                      nullptr, ln1_g, ln1_b, h1, h1h, n);

    // ---- bottleneck down ----
    launch_tgemm32(h1h, wth + WTH_DN, nullptr, tmp, n, DIM, DIM);
    ln_kernel<<<lnBlocks, 256>>>(tmp, nullptr, lnd_g, lnd_b, z, zh, n);

    // ---- GAT layer 2 (residual z inside fused gather-LN) ----
    launch_tgemm16(zh, wth + WTH_L2, xlr, n, 512, DIM);
    gatln_kernel<<<nodeBlocks, 256>>>(xlr, off, epack, We2, att2, bg2,
                                      z, ln2_g, ln2_b, nullptr, z2h, n);

    // ---- up projection + final LN ----
    launch_tgemm32(z2h, wth + WTH_UP, nullptr, tmp, n, DIM, DIM);
    ln_kernel<<<lnBlocks, 256>>>(tmp, h1, lnu_g, lnu_b, out_h, outh, n);

    // ---- classifier ----
    launch_tgemm32(outh, wth + WTH_CLS, b_cls, out_logits, n, 1000, DIM);
}

// round 16
// speedup vs baseline: 1.0487x; 1.0070x over previous
#include <cuda_runtime.h>
#include <cuda_fp16.h>
#include <math.h>
#include <stdint.h>

// ---------------- problem constants ----------------
#define NMAX 20000
#define EMAX 320000
#define DIM 256
#define HEADS 8

// ---------------- scratch ----------------
__device__ __align__(16) __half g_xlr[NMAX * 512];      // fp16: [n,0:256]=xl, [n,256:512]=xr
__device__ __align__(16) float g_h1[NMAX * DIM];
__device__ __align__(16) float g_z[NMAX * DIM];
__device__ __align__(16) float g_tmp[NMAX * DIM];
// fp16 activation copies (GEMM A operands)
__device__ __align__(16) __half g_h0h[NMAX * 64];
__device__ __align__(16) __half g_h1h[NMAX * DIM];
__device__ __align__(16) __half g_zh[NMAX * DIM];
__device__ __align__(16) __half g_z2h[NMAX * DIM];
__device__ __align__(16) __half g_outh[NMAX * DIM];
// per-dst linked list
__device__ int   g_head[NMAX];
__device__ __align__(16) int4 g_enode[EMAX];   // .x=next, .y=src, .z=ea bits
// fp16 transposed weights
#define WTH_L1  0
#define WTH_DN  32768
#define WTH_L2  98304
#define WTH_UP  229376
#define WTH_CLS 294912
#define WTH_TOTAL (294912 + 256000)
__device__ __align__(16) __half g_wth[WTH_TOTAL];

// ---------------- helpers ----------------
__device__ __forceinline__ float warpReduceSum(float v) {
#pragma unroll
    for (int o = 16; o > 0; o >>= 1) v += __shfl_xor_sync(0xffffffffu, v, o);
    return v;
}

__device__ __forceinline__ float leaky(float v) { return v > 0.f ? v : 0.2f * v; }

__device__ __forceinline__ uint32_t smem_u32(const void* p) {
    uint32_t a;
    asm("{ .reg .u64 t; cvta.to.shared.u64 t, %1; cvt.u32.u64 %0, t; }" : "=r"(a) : "l"(p));
    return a;
}

__device__ __forceinline__ void cpasync16(uint32_t dst, const void* src, bool valid) {
    int sz = valid ? 16 : 0;
    asm volatile("cp.async.cg.shared.global [%0], [%1], 16, %2;"
                 :: "r"(dst), "l"(src), "r"(sz));
}
__device__ __forceinline__ void cpasync_commit() { asm volatile("cp.async.commit_group;"); }
__device__ __forceinline__ void cpasync_wait0() { asm volatile("cp.async.wait_group 0;"); }

#define LDMATRIX_X4(r0, r1, r2, r3, addr) \
    asm volatile("ldmatrix.sync.aligned.m8n8.x4.shared.b16 {%0,%1,%2,%3}, [%4];" \
                 : "=r"(r0), "=r"(r1), "=r"(r2), "=r"(r3) : "r"(addr))

// ---------------- fused prologue: head=-1 + transpose-all + inproj --------------------
struct TransDesc { const float* in; __half* out; int Kreal, Kpad, N, blkStart, nx; };
struct PrologueArgs {
    TransDesc d[7];
    int tcum;
    int zb;
    int* head;
    const float* x; const float* W_in; const float* b_in; __half* h0h;
    int n;
};

__global__ void prologue_kernel(PrologueArgs pa) {
    __shared__ float sbuf[32 * 33];
    int bid = blockIdx.x;
    int tid = threadIdx.x;
    if (bid < pa.zb) {
        int i = bid * 256 + tid;
        if (i < pa.n) pa.head[i] = -1;
        return;
    }
    bid -= pa.zb;
    if (bid < pa.tcum) {
        float (*t)[33] = (float(*)[33])sbuf;
        int di = 0;
#pragma unroll
        for (int i = 1; i < 7; i++) if (bid >= pa.d[i].blkStart) di = i;
        const TransDesc& D = pa.d[di];
        int rem = bid - D.blkStart;
        int bx = (rem % D.nx) * 32, by = (rem / D.nx) * 32;
        int tx = tid & 31, ty = tid >> 5;
        int x = bx + tx, y = by + ty;
#pragma unroll
        for (int i = 0; i < 32; i += 8)
            t[ty + i][tx] = (x < D.N && y + i < D.Kreal) ? D.in[(size_t)(y + i) * D.N + x] : 0.f;
        __syncthreads();
        x = by + tx;
        y = bx + ty;
#pragma unroll
        for (int i = 0; i < 32; i += 8)
            if (x < D.Kpad && y + i < D.N)
                D.out[(size_t)(y + i) * D.Kpad + x] = __float2half(t[tx][ty + i]);
        return;
    }
    bid -= pa.tcum;
    {
        float* sW = sbuf;
        float* sb = sbuf + 576;
        for (int i = tid; i < 18 * 32; i += 256) sW[i] = pa.W_in[i];
        if (tid < 32) sb[tid] = pa.b_in[tid];
        __syncthreads();
        int row = bid * 8 + (tid >> 5);
        int col = tid & 31;
        if (row >= pa.n) return;
        const float* xr = pa.x + (size_t)row * 18;
        float v = sb[col];
#pragma unroll
        for (int k = 0; k < 18; k++) v += xr[k] * sW[k * 32 + col];
        pa.h0h[(size_t)row * 64 + col] = __float2half(v);
        pa.h0h[(size_t)row * 64 + 32 + col] = __float2half(0.f);
    }
}

// ---------------- linked-list build: one pass, no scan ----------------
__global__ void list_build_kernel(const int* __restrict__ src, const int* __restrict__ dst,
                                  const float* __restrict__ ea,
                                  int* __restrict__ head, int4* __restrict__ enode, int E) {
    int e = blockIdx.x * blockDim.x + threadIdx.x;
    if (e >= E) return;
    int d = dst[e];
    int h = atomicExch(&head[d], e);
    enode[e] = make_int4(h, src[e], __float_as_int(ea[e]), 0);
}

// ---------------- fp16 mma.sync GEMM: out = A[M,K] @ WT[N,K]^T (+bias), fp32 accum ------
#define SWW 36
#define CHUNK_WORDS (128 * SWW)

extern __shared__ uint32_t g_dynsmem_u[];

__global__ __launch_bounds__(256)
void mma_gemm_h(const __half* __restrict__ A, const __half* __restrict__ WT,
                const float* __restrict__ bias, float* __restrict__ C32,
                __half* __restrict__ C16, int M, int N, int K) {
    const int tid = threadIdx.x;
    const int wid = tid >> 5, lane = tid & 31;
    const int gid = lane >> 2, tig = lane & 3;
    const int wm = (wid >> 2) * 64, wn = (wid & 3) * 32;
    const int m0 = blockIdx.y * 128, n0 = blockIdx.x * 128;

    float acc[4][4][4];
#pragma unroll
    for (int mi = 0; mi < 4; mi++)
#pragma unroll
        for (int ni = 0; ni < 4; ni++)
#pragma unroll
            for (int q = 0; q < 4; q++) acc[mi][ni][q] = 0.f;

    const int nc = (K + 63) >> 6;
    uint32_t aAddr[2], bAddr[2];
    aAddr[0] = smem_u32(g_dynsmem_u);
    bAddr[0] = aAddr[0] + CHUNK_WORDS * 4;
    aAddr[1] = aAddr[0] + 2 * CHUNK_WORDS * 4;
    bAddr[1] = aAddr[0] + 3 * CHUNK_WORDS * 4;

    const uint32_t aOff = (uint32_t)((wm + (lane & 15)) * 144 + (lane >> 4) * 16);
    const uint32_t bOff = (uint32_t)((wn + (lane & 7) + ((lane >> 4) << 3)) * 144
                                     + ((lane >> 3) & 1) * 16);

    auto issue = [&](int c, int b) {
        int k0 = c << 6;
        int Kc = K - k0; if (Kc > 64) Kc = 64;
#pragma unroll
        for (int i = 0; i < 4; i++) {
            int idx = tid + i * 256;
            int row = idx >> 3, q = idx & 7;
            uint32_t soff = (uint32_t)(row * 144 + q * 16);
            bool kv = (q * 8) < Kc;
            cpasync16(aAddr[b] + soff, A + (size_t)(m0 + row) * K + k0 + q * 8,
                      kv && (m0 + row < M));
            cpasync16(bAddr[b] + soff, WT + (size_t)(n0 + row) * K + k0 + q * 8,
                      kv && (n0 + row < N));
        }
        cpasync_commit();
    };

    issue(0, 0);
    for (int c = 0; c < nc; c++) {
        int cur = c & 1;
        cpasync_wait0();
        __syncthreads();
        if (c + 1 < nc) issue(c + 1, cur ^ 1);
        uint32_t aB = aAddr[cur] + aOff;
        uint32_t bB = bAddr[cur] + bOff;
        int Kc = K - (c << 6); if (Kc > 64) Kc = 64;
#pragma unroll
        for (int ks = 0; ks < 4; ks++) {
            if (ks * 16 < Kc) {
                uint32_t af[4][4], bf[4][2];
#pragma unroll
                for (int mi = 0; mi < 4; mi++)
                    LDMATRIX_X4(af[mi][0], af[mi][1], af[mi][2], af[mi][3],
                                aB + mi * 16 * 144 + ks * 32);
#pragma unroll
                for (int np = 0; np < 2; np++)
                    LDMATRIX_X4(bf[2 * np][0], bf[2 * np][1], bf[2 * np + 1][0], bf[2 * np + 1][1],
                                bB + np * 16 * 144 + ks * 32);
#pragma unroll
                for (int mi = 0; mi < 4; mi++)
#pragma unroll
                    for (int ni = 0; ni < 4; ni++) {
                        asm volatile(
                            "mma.sync.aligned.m16n8k16.row.col.f32.f16.f16.f32 "
                            "{%0,%1,%2,%3}, {%4,%5,%6,%7}, {%8,%9}, {%0,%1,%2,%3};"
                            : "+f"(acc[mi][ni][0]), "+f"(acc[mi][ni][1]),
                              "+f"(acc[mi][ni][2]), "+f"(acc[mi][ni][3])
                            : "r"(af[mi][0]), "r"(af[mi][1]), "r"(af[mi][2]), "r"(af[mi][3]),
                              "r"(bf[ni][0]), "r"(bf[ni][1]));
                    }
            }
        }
    }

#pragma unroll
    for (int mi = 0; mi < 4; mi++) {
        int r0 = m0 + wm + mi * 16 + gid;
        int r1 = r0 + 8;
#pragma unroll
        for (int ni = 0; ni < 4; ni++) {
            int col = n0 + wn + ni * 8 + tig * 2;
            if (col >= N) continue;
            if (C16) {
                if (r0 < M)
                    *(__half2*)(C16 + (size_t)r0 * N + col) =
                        __floats2half2_rn(acc[mi][ni][0], acc[mi][ni][1]);
                if (r1 < M)
                    *(__half2*)(C16 + (size_t)r1 * N + col) =
                        __floats2half2_rn(acc[mi][ni][2], acc[mi][ni][3]);
            } else {
                float bx = 0.f, by = 0.f;
                if (bias) { bx = bias[col]; by = bias[col + 1]; }
                if (r0 < M)
                    *(float2*)(C32 + (size_t)r0 * N + col) =
                        make_float2(acc[mi][ni][0] + bx, acc[mi][ni][1] + by);
                if (r1 < M)
                    *(float2*)(C32 + (size_t)r1 * N + col) =
                        make_float2(acc[mi][ni][2] + bx, acc[mi][ni][3] + by);
            }
        }
    }
}

// ---------------- fused linked-list gather GAT + LayerNorm (fp16 xlr) -------------------
// warp per dst node; walks the per-node edge list with node(i+2)/row(i+1) in flight.
__global__ void gatln_kernel(const __half* __restrict__ xlr,
                             const int* __restrict__ head, const int4* __restrict__ enode,
                             const float* __restrict__ We, const float* __restrict__ att,
                             const float* __restrict__ bias, const float* __restrict__ res,
                             const float* __restrict__ lng, const float* __restrict__ lnb,
                             float* __restrict__ out32, __half* __restrict__ out16, int n) {
    int d = (blockIdx.x * blockDim.x + threadIdx.x) >> 5;
    int lane = threadIdx.x & 31;
    if (d >= n) return;
    float r[8], w[8], t[8];
    {
        uint4 rv = ((const uint4*)(xlr + (size_t)d * 512 + 256))[lane];
        const __half2* hp = (const __half2*)&rv;
#pragma unroll
        for (int k = 0; k < 4; k++) {
            float2 f = __half22float2(hp[k]);
            r[2 * k] = f.x; r[2 * k + 1] = f.y;
        }
        float4 wa = ((const float4*)We)[2 * lane], wb = ((const float4*)We)[2 * lane + 1];
        w[0] = wa.x; w[1] = wa.y; w[2] = wa.z; w[3] = wa.w;
        w[4] = wb.x; w[5] = wb.y; w[6] = wb.z; w[7] = wb.w;
        float4 ta = ((const float4*)att)[2 * lane], tb = ((const float4*)att)[2 * lane + 1];
        t[0] = ta.x; t[1] = ta.y; t[2] = ta.z; t[3] = ta.w;
        t[4] = tb.x; t[5] = tb.y; t[6] = tb.z; t[7] = tb.w;
    }
    float acc[8];
#pragma unroll
    for (int k = 0; k < 8; k++) acc[k] = 0.f;
    float ss = 0.f;
    int e0 = head[d];
    if (e0 >= 0) {
        int4 nd = enode[e0];                                        // node 0
        uint4 row = ((const uint4*)(xlr + (size_t)nd.y * 512))[lane]; // row 0 in flight
        int e1 = nd.x;
        int4 nd1;
        if (e1 >= 0) nd1 = enode[e1];                               // node 1 in flight
        while (true) {
            uint4 rowN;
            int e2 = -1;
            int4 nd2;
            if (e1 >= 0) {
                rowN = ((const uint4*)(xlr + (size_t)nd1.y * 512))[lane]; // row i+1
                e2 = nd1.x;
                if (e2 >= 0) nd2 = enode[e2];                             // node i+2
            }
            float ca = __int_as_float(nd.z);
            float l[8];
            const __half2* hp = (const __half2*)&row;
#pragma unroll
            for (int k = 0; k < 4; k++) {
                float2 f = __half22float2(hp[k]);
                l[2 * k] = f.x; l[2 * k + 1] = f.y;
            }
            float p = 0.f;
#pragma unroll
            for (int k = 0; k < 8; k++) p += leaky(l[k] + r[k] + ca * w[k]) * t[k];
            p += __shfl_xor_sync(0xffffffffu, p, 1);
            p += __shfl_xor_sync(0xffffffffu, p, 2);
            float e = __expf(p);
#pragma unroll
            for (int k = 0; k < 8; k++) acc[k] += e * l[k];
            ss += e;
            if (e1 < 0) break;
            nd = nd1; row = rowN;
            e1 = e2; nd1 = nd2;
        }
    }
    float iv = 1.f / (ss + 1e-16f);
    float v[8];
    {
        float4 ba = ((const float4*)bias)[2 * lane], bb = ((const float4*)bias)[2 * lane + 1];
        v[0] = acc[0] * iv + ba.x; v[1] = acc[1] * iv + ba.y;
        v[2] = acc[2] * iv + ba.z; v[3] = acc[3] * iv + ba.w;
        v[4] = acc[4] * iv + bb.x; v[5] = acc[5] * iv + bb.y;
        v[6] = acc[6] * iv + bb.z; v[7] = acc[7] * iv + bb.w;
    }
    if (res) {
        float4 ra = ((const float4*)(res + (size_t)d * DIM))[2 * lane];
        float4 rb = ((const float4*)(res + (size_t)d * DIM))[2 * lane + 1];
        v[0] += ra.x; v[1] += ra.y; v[2] += ra.z; v[3] += ra.w;
        v[4] += rb.x; v[5] += rb.y; v[6] += rb.z; v[7] += rb.w;
    }
    float sum = 0.f;
#pragma unroll
    for (int k = 0; k < 8; k++) sum += v[k];
    sum = warpReduceSum(sum);
    float mu = sum * (1.f / 256.f);
    float var = 0.f;
#pragma unroll
    for (int k = 0; k < 8; k++) { float dd = v[k] - mu; var += dd * dd; }
    var = warpReduceSum(var) * (1.f / 256.f);
    float inv = rsqrtf(var + 1e-5f);
    float4 ga = ((const float4*)lng)[2 * lane], gb = ((const float4*)lng)[2 * lane + 1];
    float4 ca4 = ((const float4*)lnb)[2 * lane], cb4 = ((const float4*)lnb)[2 * lane + 1];
    float o[8];
    o[0] = (v[0] - mu) * inv * ga.x + ca4.x; o[1] = (v[1] - mu) * inv * ga.y + ca4.y;
    o[2] = (v[2] - mu) * inv * ga.z + ca4.z; o[3] = (v[3] - mu) * inv * ga.w + ca4.w;
    o[4] = (v[4] - mu) * inv * gb.x + cb4.x; o[5] = (v[5] - mu) * inv * gb.y + cb4.y;
    o[6] = (v[6] - mu) * inv * gb.z + cb4.z; o[7] = (v[7] - mu) * inv * gb.w + cb4.w;
    if (out32) {
        float4* op = (float4*)(out32 + (size_t)d * DIM);
        op[2 * lane]     = make_float4(o[0], o[1], o[2], o[3]);
        op[2 * lane + 1] = make_float4(o[4], o[5], o[6], o[7]);
    }
    if (out16) {
        uint4 pk16;
        __half2 h0 = __floats2half2_rn(o[0], o[1]), h1 = __floats2half2_rn(o[2], o[3]);
        __half2 h2 = __floats2half2_rn(o[4], o[5]), h3 = __floats2half2_rn(o[6], o[7]);
        pk16.x = *(uint32_t*)&h0; pk16.y = *(uint32_t*)&h1;
        pk16.z = *(uint32_t*)&h2; pk16.w = *(uint32_t*)&h3;
        ((uint4*)(out16 + (size_t)d * DIM))[lane] = pk16;
    }
}

// ---------------- layernorm (dim=256); optional residual; fp32 + fp16 outputs ----------
__global__ void ln_kernel(const float* __restrict__ x, const float* __restrict__ res,
                          const float* __restrict__ g, const float* __restrict__ b,
                          float* __restrict__ out32, __half* __restrict__ out16, int n) {
    int row = blockIdx.x * 8 + (threadIdx.x >> 5);
    int lane = threadIdx.x & 31;
    if (row >= n) return;
    const float4* xr4 = (const float4*)(x + (size_t)row * DIM);
    const float4* rs4 = res ? (const float4*)(res + (size_t)row * DIM) : nullptr;
    float4 v[2];
    float sum = 0.f;
#pragma unroll
    for (int k = 0; k < 2; k++) {
        int q = k * 32 + lane;
        float4 t = xr4[q];
        if (rs4) { float4 r = rs4[q]; t.x += r.x; t.y += r.y; t.z += r.z; t.w += r.w; }
        v[k] = t;
        sum += t.x + t.y + t.z + t.w;
    }
    sum = warpReduceSum(sum);
    float mu = sum * (1.f / 256.f);
    float var = 0.f;
#pragma unroll
    for (int k = 0; k < 2; k++) {
        float dx = v[k].x - mu, dy = v[k].y - mu, dz = v[k].z - mu, dw = v[k].w - mu;
        var += dx * dx + dy * dy + dz * dz + dw * dw;
    }
    var = warpReduceSum(var) * (1.f / 256.f);
    float inv = rsqrtf(var + 1e-5f);
    const float4* g4 = (const float4*)g;
    const float4* b4 = (const float4*)b;
#pragma unroll
    for (int k = 0; k < 2; k++) {
        int q = k * 32 + lane;
        float4 gg = g4[q], bb = b4[q];
        float4 o = make_float4((v[k].x - mu) * inv * gg.x + bb.x,
                               (v[k].y - mu) * inv * gg.y + bb.y,
                               (v[k].z - mu) * inv * gg.z + bb.z,
                               (v[k].w - mu) * inv * gg.w + bb.w);
        if (out32) ((float4*)(out32 + (size_t)row * DIM))[q] = o;
        if (out16) {
            __half2* o16 = (__half2*)(out16 + (size_t)row * DIM);
            o16[q * 2]     = __floats2half2_rn(o.x, o.y);
            o16[q * 2 + 1] = __floats2half2_rn(o.z, o.w);
        }
    }
}

// ---------------- host ----------------
#define DYN_SMEM (4 * CHUNK_WORDS * sizeof(uint32_t))   // 73728 bytes

static inline void launch_tgemm32(const __half* A, const __half* WT, const float* bias,
                                  float* C, int M, int N, int K) {
    dim3 grid((N + 127) / 128, (M + 127) / 128);
    mma_gemm_h<<<grid, 256, DYN_SMEM>>>(A, WT, bias, C, nullptr, M, N, K);
}
static inline void launch_tgemm16(const __half* A, const __half* WT, __half* C,
                                  int M, int N, int K) {
    dim3 grid((N + 127) / 128, (M + 127) / 128);
    mma_gemm_h<<<grid, 256, DYN_SMEM>>>(A, WT, nullptr, nullptr, C, M, N, K);
}

extern "C" void kernel_launch(void* const* d_in, const int* in_sizes, int n_in,
                              void* d_out, int out_size) {
    cudaFuncSetAttribute(mma_gemm_h, cudaFuncAttributeMaxDynamicSharedMemorySize, DYN_SMEM);

    const float* x_gnn = (const float*)d_in[0];
    const int*   eidx  = (const int*)d_in[1];
    const float* eattr = (const float*)d_in[2];
    const float* W_in  = (const float*)d_in[3];
    const float* b_in  = (const float*)d_in[4];
    const float* Wl1   = (const float*)d_in[5];
    const float* Wr1   = (const float*)d_in[6];
    const float* We1   = (const float*)d_in[7];
    const float* att1  = (const float*)d_in[8];
    const float* bg1   = (const float*)d_in[9];
    const float* ln1_g = (const float*)d_in[10];
    const float* ln1_b = (const float*)d_in[11];
    const float* W_down= (const float*)d_in[12];
    const float* lnd_g = (const float*)d_in[13];
    const float* lnd_b = (const float*)d_in[14];
    const float* Wl2   = (const float*)d_in[15];
    const float* Wr2   = (const float*)d_in[16];
    const float* We2   = (const float*)d_in[17];
    const float* att2  = (const float*)d_in[18];
    const float* bg2   = (const float*)d_in[19];
    const float* ln2_g = (const float*)d_in[20];
    const float* ln2_b = (const float*)d_in[21];
    const float* W_up  = (const float*)d_in[22];
    const float* lnu_g = (const float*)d_in[23];
    const float* lnu_b = (const float*)d_in[24];
    const float* W_cls = (const float*)d_in[25];
    const float* b_cls = (const float*)d_in[26];

    const int n = in_sizes[0] / 18;        // 20000
    const int E = in_sizes[1] / 2;         // 320000
    const int* src = eidx;
    const int* dst = eidx + E;

    float *h1, *z, *tmp;
    __half *xlr, *h0h, *h1h, *zh, *z2h, *outh, *wth;
    int *head;
    int4 *enode;
    cudaGetSymbolAddress((void**)&xlr, g_xlr);
    cudaGetSymbolAddress((void**)&h1, g_h1);
    cudaGetSymbolAddress((void**)&z, g_z);
    cudaGetSymbolAddress((void**)&tmp, g_tmp);
    cudaGetSymbolAddress((void**)&h0h, g_h0h);
    cudaGetSymbolAddress((void**)&h1h, g_h1h);
    cudaGetSymbolAddress((void**)&zh, g_zh);
    cudaGetSymbolAddress((void**)&z2h, g_z2h);
    cudaGetSymbolAddress((void**)&outh, g_outh);
    cudaGetSymbolAddress((void**)&wth, g_wth);
    cudaGetSymbolAddress((void**)&head, g_head);
    cudaGetSymbolAddress((void**)&enode, g_enode);

    float* out_logits = (float*)d_out;
    float* out_h = (float*)d_out + (size_t)n * 1000;

    const int lnBlocks = (n + 7) / 8;
    const int nodeBlocks = (n + 7) / 8;

    // ---- fused prologue: head=-1 + weight transposes + input projection ----
    {
        PrologueArgs pa;
        auto set = [&](int i, const float* in, __half* out, int Kreal, int Kpad, int N, int& cum) {
            pa.d[i].in = in; pa.d[i].out = out;
            pa.d[i].Kreal = Kreal; pa.d[i].Kpad = Kpad; pa.d[i].N = N;
            pa.d[i].blkStart = cum; pa.d[i].nx = (N + 31) / 32;
            cum += pa.d[i].nx * ((Kpad + 31) / 32);
        };
        int cum = 0;
        set(0, Wl1,    wth + WTH_L1,            32, 64, DIM, cum);
        set(1, Wr1,    wth + WTH_L1 + 256 * 64, 32, 64, DIM, cum);
        set(2, W_down, wth + WTH_DN,  DIM, DIM, DIM, cum);
        set(3, Wl2,    wth + WTH_L2,  DIM, DIM, DIM, cum);
        set(4, Wr2,    wth + WTH_L2 + 256 * 256, DIM, DIM, DIM, cum);
        set(5, W_up,   wth + WTH_UP,  DIM, DIM, DIM, cum);
        set(6, W_cls,  wth + WTH_CLS, DIM, DIM, 1000, cum);
        pa.tcum = cum;
        pa.zb = (n + 255) / 256;
        pa.head = head;
        pa.x = x_gnn; pa.W_in = W_in; pa.b_in = b_in; pa.h0h = h0h;
        pa.n = n;
        int total = pa.zb + cum + (n + 7) / 8;
        prologue_kernel<<<total, 256>>>(pa);
    }

    // ---- GAT layer 1 GEMM (independent of edge list) ----
    launch_tgemm16(h0h, wth + WTH_L1, xlr, n, 512, 64);

    // ---- linked-list build (one pass; replaces hist+scan+scatter) ----
    list_build_kernel<<<(E + 255) / 256, 256>>>(src, dst, eattr, head, enode, E);

    // ---- GAT layer 1 gather+LN ----
    gatln_kernel<<<nodeBlocks, 256>>>(xlr, head, enode, We1, att1, bg1,
                                      nullptr, ln1_g, ln1_b, h1, h1h, n);

    // ---- bottleneck down ----
    launch_tgemm32(h1h, wth + WTH_DN, nullptr, tmp, n, DIM, DIM);
    ln_kernel<<<lnBlocks, 256>>>(tmp, nullptr, lnd_g, lnd_b, z, zh, n);

    // ---- GAT layer 2 (residual z inside fused gather-LN) ----
    launch_tgemm16(zh, wth + WTH_L2, xlr, n, 512, DIM);
    gatln_kernel<<<nodeBlocks, 256>>>(xlr, head, enode, We2, att2, bg2,
                                      z, ln2_g, ln2_b, nullptr, z2h, n);

    // ---- up projection + final LN ----
    launch_tgemm32(z2h, wth + WTH_UP, nullptr, tmp, n, DIM, DIM);
    ln_kernel<<<lnBlocks, 256>>>(tmp, h1, lnu_g, lnu_b, out_h, outh, n);

    // ---- classifier ----
    launch_tgemm32(outh, wth + WTH_CLS, b_cls, out_logits, n, 1000, DIM);
}

// round 17
// speedup vs baseline: 1.1084x; 1.0569x over previous
#include <cuda_runtime.h>
#include <cuda_fp16.h>
#include <math.h>
#include <stdint.h>

// ---------------- problem constants ----------------
#define NMAX 20000
#define EMAX 320000
#define DIM 256
#define HEADS 8

// ---------------- scratch ----------------
__device__ __align__(16) __half g_xlr[NMAX * 512];      // fp16: [n,0:256]=xl, [n,256:512]=xr
__device__ __align__(16) float g_h1[NMAX * DIM];
__device__ __align__(16) float g_z[NMAX * DIM];
__device__ __align__(16) float g_tmp[NMAX * DIM];
// fp16 activation copies (GEMM A operands)
__device__ __align__(16) __half g_h0h[NMAX * 64];
__device__ __align__(16) __half g_h1h[NMAX * DIM];
__device__ __align__(16) __half g_zh[NMAX * DIM];
__device__ __align__(16) __half g_z2h[NMAX * DIM];
__device__ __align__(16) __half g_outh[NMAX * DIM];
// per-dst linked list
__device__ int   g_head[NMAX];
__device__ __align__(16) int4 g_enode[EMAX];   // .x=next, .y=src, .z=ea bits
// fp16 transposed weights
#define WTH_L1  0
#define WTH_DN  32768
#define WTH_L2  98304
#define WTH_UP  229376
#define WTH_CLS 294912
#define WTH_TOTAL (294912 + 256000)
__device__ __align__(16) __half g_wth[WTH_TOTAL];

// ---------------- helpers ----------------
__device__ __forceinline__ float warpReduceSum(float v) {
#pragma unroll
    for (int o = 16; o > 0; o >>= 1) v += __shfl_xor_sync(0xffffffffu, v, o);
    return v;
}

__device__ __forceinline__ uint32_t smem_u32(const void* p) {
    uint32_t a;
    asm("{ .reg .u64 t; cvta.to.shared.u64 t, %1; cvt.u32.u64 %0, t; }" : "=r"(a) : "l"(p));
    return a;
}

__device__ __forceinline__ void cpasync16(uint32_t dst, const void* src, bool valid) {
    int sz = valid ? 16 : 0;
    asm volatile("cp.async.cg.shared.global [%0], [%1], 16, %2;"
                 :: "r"(dst), "l"(src), "r"(sz));
}
__device__ __forceinline__ void cpasync_commit() { asm volatile("cp.async.commit_group;"); }
__device__ __forceinline__ void cpasync_wait0() { asm volatile("cp.async.wait_group 0;"); }

#define LDMATRIX_X4(r0, r1, r2, r3, addr) \
    asm volatile("ldmatrix.sync.aligned.m8n8.x4.shared.b16 {%0,%1,%2,%3}, [%4];" \
                 : "=r"(r0), "=r"(r1), "=r"(r2), "=r"(r3) : "r"(addr))

// ---------------- fused prologue: head=-1 + transpose-all + inproj --------------------
struct TransDesc { const float* in; __half* out; int Kreal, Kpad, N, blkStart, nx; };
struct PrologueArgs {
    TransDesc d[7];
    int tcum;
    int zb;
    int* head;
    const float* x; const float* W_in; const float* b_in; __half* h0h;
    int n;
};

__global__ void prologue_kernel(PrologueArgs pa) {
    __shared__ float sbuf[32 * 33];
    int bid = blockIdx.x;
    int tid = threadIdx.x;
    if (bid < pa.zb) {
        int i = bid * 256 + tid;
        if (i < pa.n) pa.head[i] = -1;
        return;
    }
    bid -= pa.zb;
    if (bid < pa.tcum) {
        float (*t)[33] = (float(*)[33])sbuf;
        int di = 0;
#pragma unroll
        for (int i = 1; i < 7; i++) if (bid >= pa.d[i].blkStart) di = i;
        const TransDesc& D = pa.d[di];
        int rem = bid - D.blkStart;
        int bx = (rem % D.nx) * 32, by = (rem / D.nx) * 32;
        int tx = tid & 31, ty = tid >> 5;
        int x = bx + tx, y = by + ty;
#pragma unroll
        for (int i = 0; i < 32; i += 8)
            t[ty + i][tx] = (x < D.N && y + i < D.Kreal) ? D.in[(size_t)(y + i) * D.N + x] : 0.f;
        __syncthreads();
        x = by + tx;
        y = bx + ty;
#pragma unroll
        for (int i = 0; i < 32; i += 8)
            if (x < D.Kpad && y + i < D.N)
                D.out[(size_t)(y + i) * D.Kpad + x] = __float2half(t[tx][ty + i]);
        return;
    }
    bid -= pa.tcum;
    {
        float* sW = sbuf;
        float* sb = sbuf + 576;
        for (int i = tid; i < 18 * 32; i += 256) sW[i] = pa.W_in[i];
        if (tid < 32) sb[tid] = pa.b_in[tid];
        __syncthreads();
        int row = bid * 8 + (tid >> 5);
        int col = tid & 31;
        if (row >= pa.n) return;
        const float* xr = pa.x + (size_t)row * 18;
        float v = sb[col];
#pragma unroll
        for (int k = 0; k < 18; k++) v += xr[k] * sW[k * 32 + col];
        pa.h0h[(size_t)row * 64 + col] = __float2half(v);
        pa.h0h[(size_t)row * 64 + 32 + col] = __float2half(0.f);
    }
}

// ---------------- linked-list build: one pass, no scan ----------------
__global__ void list_build_kernel(const int* __restrict__ src, const int* __restrict__ dst,
                                  const float* __restrict__ ea,
                                  int* __restrict__ head, int4* __restrict__ enode, int E) {
    int e = blockIdx.x * blockDim.x + threadIdx.x;
    if (e >= E) return;
    int d = dst[e];
    int h = atomicExch(&head[d], e);
    enode[e] = make_int4(h, src[e], __float_as_int(ea[e]), 0);
}

// ---------------- fp16 mma.sync GEMM: out = A[M,K] @ WT[N,K]^T (+bias), fp32 accum ------
#define SWW 36
#define CHUNK_WORDS (128 * SWW)

extern __shared__ uint32_t g_dynsmem_u[];

__global__ __launch_bounds__(256)
void mma_gemm_h(const __half* __restrict__ A, const __half* __restrict__ WT,
                const float* __restrict__ bias, float* __restrict__ C32,
                __half* __restrict__ C16, int M, int N, int K) {
    const int tid = threadIdx.x;
    const int wid = tid >> 5, lane = tid & 31;
    const int gid = lane >> 2, tig = lane & 3;
    const int wm = (wid >> 2) * 64, wn = (wid & 3) * 32;
    const int m0 = blockIdx.y * 128, n0 = blockIdx.x * 128;

    float acc[4][4][4];
#pragma unroll
    for (int mi = 0; mi < 4; mi++)
#pragma unroll
        for (int ni = 0; ni < 4; ni++)
#pragma unroll
            for (int q = 0; q < 4; q++) acc[mi][ni][q] = 0.f;

    const int nc = (K + 63) >> 6;
    uint32_t aAddr[2], bAddr[2];
    aAddr[0] = smem_u32(g_dynsmem_u);
    bAddr[0] = aAddr[0] + CHUNK_WORDS * 4;
    aAddr[1] = aAddr[0] + 2 * CHUNK_WORDS * 4;
    bAddr[1] = aAddr[0] + 3 * CHUNK_WORDS * 4;

    const uint32_t aOff = (uint32_t)((wm + (lane & 15)) * 144 + (lane >> 4) * 16);
    const uint32_t bOff = (uint32_t)((wn + (lane & 7) + ((lane >> 4) << 3)) * 144
                                     + ((lane >> 3) & 1) * 16);

    auto issue = [&](int c, int b) {
        int k0 = c << 6;
        int Kc = K - k0; if (Kc > 64) Kc = 64;
#pragma unroll
        for (int i = 0; i < 4; i++) {
            int idx = tid + i * 256;
            int row = idx >> 3, q = idx & 7;
            uint32_t soff = (uint32_t)(row * 144 + q * 16);
            bool kv = (q * 8) < Kc;
            cpasync16(aAddr[b] + soff, A + (size_t)(m0 + row) * K + k0 + q * 8,
                      kv && (m0 + row < M));
            cpasync16(bAddr[b] + soff, WT + (size_t)(n0 + row) * K + k0 + q * 8,
                      kv && (n0 + row < N));
        }
        cpasync_commit();
    };

    issue(0, 0);
    for (int c = 0; c < nc; c++) {
        int cur = c & 1;
        cpasync_wait0();
        __syncthreads();
        if (c + 1 < nc) issue(c + 1, cur ^ 1);
        uint32_t aB = aAddr[cur] + aOff;
        uint32_t bB = bAddr[cur] + bOff;
        int Kc = K - (c << 6); if (Kc > 64) Kc = 64;
#pragma unroll
        for (int ks = 0; ks < 4; ks++) {
            if (ks * 16 < Kc) {
                uint32_t af[4][4], bf[4][2];
#pragma unroll
                for (int mi = 0; mi < 4; mi++)
                    LDMATRIX_X4(af[mi][0], af[mi][1], af[mi][2], af[mi][3],
                                aB + mi * 16 * 144 + ks * 32);
#pragma unroll
                for (int np = 0; np < 2; np++)
                    LDMATRIX_X4(bf[2 * np][0], bf[2 * np][1], bf[2 * np + 1][0], bf[2 * np + 1][1],
                                bB + np * 16 * 144 + ks * 32);
#pragma unroll
                for (int mi = 0; mi < 4; mi++)
#pragma unroll
                    for (int ni = 0; ni < 4; ni++) {
                        asm volatile(
                            "mma.sync.aligned.m16n8k16.row.col.f32.f16.f16.f32 "
                            "{%0,%1,%2,%3}, {%4,%5,%6,%7}, {%8,%9}, {%0,%1,%2,%3};"
                            : "+f"(acc[mi][ni][0]), "+f"(acc[mi][ni][1]),
                              "+f"(acc[mi][ni][2]), "+f"(acc[mi][ni][3])
                            : "r"(af[mi][0]), "r"(af[mi][1]), "r"(af[mi][2]), "r"(af[mi][3]),
                              "r"(bf[ni][0]), "r"(bf[ni][1]));
                    }
            }
        }
    }

#pragma unroll
    for (int mi = 0; mi < 4; mi++) {
        int r0 = m0 + wm + mi * 16 + gid;
        int r1 = r0 + 8;
#pragma unroll
        for (int ni = 0; ni < 4; ni++) {
            int col = n0 + wn + ni * 8 + tig * 2;
            if (col >= N) continue;
            if (C16) {
                if (r0 < M)
                    *(__half2*)(C16 + (size_t)r0 * N + col) =
                        __floats2half2_rn(acc[mi][ni][0], acc[mi][ni][1]);
                if (r1 < M)
                    *(__half2*)(C16 + (size_t)r1 * N + col) =
                        __floats2half2_rn(acc[mi][ni][2], acc[mi][ni][3]);
            } else {
                float bx = 0.f, by = 0.f;
                if (bias) { bx = bias[col]; by = bias[col + 1]; }
                if (r0 < M)
                    *(float2*)(C32 + (size_t)r0 * N + col) =
                        make_float2(acc[mi][ni][0] + bx, acc[mi][ni][1] + by);
                if (r1 < M)
                    *(float2*)(C32 + (size_t)r1 * N + col) =
                        make_float2(acc[mi][ni][2] + bx, acc[mi][ni][3] + by);
            }
        }
    }
}

// ---------------- fused linked-list gather GAT + LayerNorm, half2 score path -----------
__global__ void gatln_kernel(const __half* __restrict__ xlr,
                             const int* __restrict__ head, const int4* __restrict__ enode,
                             const float* __restrict__ We, const float* __restrict__ att,
                             const float* __restrict__ bias, const float* __restrict__ res,
                             const float* __restrict__ lng, const float* __restrict__ lnb,
                             float* __restrict__ out32, __half* __restrict__ out16, int n) {
    int d = (blockIdx.x * blockDim.x + threadIdx.x) >> 5;
    int lane = threadIdx.x & 31;
    if (d >= n) return;
    __half2 r2[4], w2[4], t2[4];
    {
        uint4 rv = ((const uint4*)(xlr + (size_t)d * 512 + 256))[lane];
        const __half2* hp = (const __half2*)&rv;
#pragma unroll
        for (int k = 0; k < 4; k++) r2[k] = hp[k];
        float4 wa = ((const float4*)We)[2 * lane], wb = ((const float4*)We)[2 * lane + 1];
        w2[0] = __floats2half2_rn(wa.x, wa.y); w2[1] = __floats2half2_rn(wa.z, wa.w);
        w2[2] = __floats2half2_rn(wb.x, wb.y); w2[3] = __floats2half2_rn(wb.z, wb.w);
        float4 ta = ((const float4*)att)[2 * lane], tb = ((const float4*)att)[2 * lane + 1];
        t2[0] = __floats2half2_rn(ta.x, ta.y); t2[1] = __floats2half2_rn(ta.z, ta.w);
        t2[2] = __floats2half2_rn(tb.x, tb.y); t2[3] = __floats2half2_rn(tb.z, tb.w);
    }
    const __half2 slope2 = __float2half2_rn(0.2f);
    float acc[8];
#pragma unroll
    for (int k = 0; k < 8; k++) acc[k] = 0.f;
    float ss = 0.f;
    int e0 = head[d];
    if (e0 >= 0) {
        int4 nd = enode[e0];
        uint4 row = ((const uint4*)(xlr + (size_t)nd.y * 512))[lane];
        int e1 = nd.x;
        int4 nd1;
        if (e1 >= 0) nd1 = enode[e1];
        while (true) {
            uint4 rowN;
            int e2 = -1;
            int4 nd2;
            if (e1 >= 0) {
                rowN = ((const uint4*)(xlr + (size_t)nd1.y * 512))[lane];
                e2 = nd1.x;
                if (e2 >= 0) nd2 = enode[e2];
            }
            __half2 ca2 = __float2half2_rn(__int_as_float(nd.z));
            const __half2* l2 = (const __half2*)&row;
            // half2 score: v = l + r + ca*w; leaky = max(v, 0.2v); p += leaky*t
            __half2 p2 = __float2half2_rn(0.f);
#pragma unroll
            for (int j = 0; j < 4; j++) {
                __half2 v2 = __hfma2(ca2, w2[j], __hadd2(l2[j], r2[j]));
                __half2 lk = __hmax2(v2, __hmul2(v2, slope2));
                p2 = __hfma2(lk, t2[j], p2);
            }
            float2 pf = __half22float2(p2);
            float p = pf.x + pf.y;
            p += __shfl_xor_sync(0xffffffffu, p, 1);
            p += __shfl_xor_sync(0xffffffffu, p, 2);
            float e = __expf(p);
            // fp32 accumulate
#pragma unroll
            for (int j = 0; j < 4; j++) {
                float2 f = __half22float2(l2[j]);
                acc[2 * j]     += e * f.x;
                acc[2 * j + 1] += e * f.y;
            }
            ss += e;
            if (e1 < 0) break;
            nd = nd1; row = rowN;
            e1 = e2; nd1 = nd2;
        }
    }
    float iv = 1.f / (ss + 1e-16f);
    float v[8];
    {
        float4 ba = ((const float4*)bias)[2 * lane], bb = ((const float4*)bias)[2 * lane + 1];
        v[0] = acc[0] * iv + ba.x; v[1] = acc[1] * iv + ba.y;
        v[2] = acc[2] * iv + ba.z; v[3] = acc[3] * iv + ba.w;
        v[4] = acc[4] * iv + bb.x; v[5] = acc[5] * iv + bb.y;
        v[6] = acc[6] * iv + bb.z; v[7] = acc[7] * iv + bb.w;
    }
    if (res) {
        float4 ra = ((const float4*)(res + (size_t)d * DIM))[2 * lane];
        float4 rb = ((const float4*)(res + (size_t)d * DIM))[2 * lane + 1];
        v[0] += ra.x; v[1] += ra.y; v[2] += ra.z; v[3] += ra.w;
        v[4] += rb.x; v[5] += rb.y; v[6] += rb.z; v[7] += rb.w;
    }
    float sum = 0.f;
#pragma unroll
    for (int k = 0; k < 8; k++) sum += v[k];
    sum = warpReduceSum(sum);
    float mu = sum * (1.f / 256.f);
    float var = 0.f;
#pragma unroll
    for (int k = 0; k < 8; k++) { float dd = v[k] - mu; var += dd * dd; }
    var = warpReduceSum(var) * (1.f / 256.f);
    float inv = rsqrtf(var + 1e-5f);
    float4 ga = ((const float4*)lng)[2 * lane], gb = ((const float4*)lng)[2 * lane + 1];
    float4 ca4 = ((const float4*)lnb)[2 * lane], cb4 = ((const float4*)lnb)[2 * lane + 1];
    float o[8];
    o[0] = (v[0] - mu) * inv * ga.x + ca4.x; o[1] = (v[1] - mu) * inv * ga.y + ca4.y;
    o[2] = (v[2] - mu) * inv * ga.z + ca4.z; o[3] = (v[3] - mu) * inv * ga.w + ca4.w;
    o[4] = (v[4] - mu) * inv * gb.x + cb4.x; o[5] = (v[5] - mu) * inv * gb.y + cb4.y;
    o[6] = (v[6] - mu) * inv * gb.z + cb4.z; o[7] = (v[7] - mu) * inv * gb.w + cb4.w;
    if (out32) {
        float4* op = (float4*)(out32 + (size_t)d * DIM);
        op[2 * lane]     = make_float4(o[0], o[1], o[2], o[3]);
        op[2 * lane + 1] = make_float4(o[4], o[5], o[6], o[7]);
    }
    if (out16) {
        uint4 pk16;
        __half2 h0 = __floats2half2_rn(o[0], o[1]), h1 = __floats2half2_rn(o[2], o[3]);
        __half2 h2 = __floats2half2_rn(o[4], o[5]), h3 = __floats2half2_rn(o[6], o[7]);
        pk16.x = *(uint32_t*)&h0; pk16.y = *(uint32_t*)&h1;
        pk16.z = *(uint32_t*)&h2; pk16.w = *(uint32_t*)&h3;
        ((uint4*)(out16 + (size_t)d * DIM))[lane] = pk16;
    }
}

// ---------------- layernorm (dim=256); optional residual; fp32 + fp16 outputs ----------
__global__ void ln_kernel(const float* __restrict__ x, const float* __restrict__ res,
                          const float* __restrict__ g, const float* __restrict__ b,
                          float* __restrict__ out32, __half* __restrict__ out16, int n) {
    int row = blockIdx.x * 8 + (threadIdx.x >> 5);
    int lane = threadIdx.x & 31;
    if (row >= n) return;
    const float4* xr4 = (const float4*)(x + (size_t)row * DIM);
    const float4* rs4 = res ? (const float4*)(res + (size_t)row * DIM) : nullptr;
    float4 v[2];
    float sum = 0.f;
#pragma unroll
    for (int k = 0; k < 2; k++) {
        int q = k * 32 + lane;
        float4 t = xr4[q];
        if (rs4) { float4 r = rs4[q]; t.x += r.x; t.y += r.y; t.z += r.z; t.w += r.w; }
        v[k] = t;
        sum += t.x + t.y + t.z + t.w;
    }
    sum = warpReduceSum(sum);
    float mu = sum * (1.f / 256.f);
    float var = 0.f;
#pragma unroll
    for (int k = 0; k < 2; k++) {
        float dx = v[k].x - mu, dy = v[k].y - mu, dz = v[k].z - mu, dw = v[k].w - mu;
        var += dx * dx + dy * dy + dz * dz + dw * dw;
    }
    var = warpReduceSum(var) * (1.f / 256.f);
    float inv = rsqrtf(var + 1e-5f);
    const float4* g4 = (const float4*)g;
    const float4* b4 = (const float4*)b;
#pragma unroll
    for (int k = 0; k < 2; k++) {
        int q = k * 32 + lane;
        float4 gg = g4[q], bb = b4[q];
        float4 o = make_float4((v[k].x - mu) * inv * gg.x + bb.x,
                               (v[k].y - mu) * inv * gg.y + bb.y,
                               (v[k].z - mu) * inv * gg.z + bb.z,
                               (v[k].w - mu) * inv * gg.w + bb.w);
        if (out32) ((float4*)(out32 + (size_t)row * DIM))[q] = o;
        if (out16) {
            __half2* o16 = (__half2*)(out16 + (size_t)row * DIM);
            o16[q * 2]     = __floats2half2_rn(o.x, o.y);
            o16[q * 2 + 1] = __floats2half2_rn(o.z, o.w);
        }
    }
}

// ---------------- host ----------------
#define DYN_SMEM (4 * CHUNK_WORDS * sizeof(uint32_t))   // 73728 bytes

static inline void launch_tgemm32(const __half* A, const __half* WT, const float* bias,
                                  float* C, int M, int N, int K) {
    dim3 grid((N + 127) / 128, (M + 127) / 128);
    mma_gemm_h<<<grid, 256, DYN_SMEM>>>(A, WT, bias, C, nullptr, M, N, K);
}
static inline void launch_tgemm16(const __half* A, const __half* WT, __half* C,
                                  int M, int N, int K) {
    dim3 grid((N + 127) / 128, (M + 127) / 128);
    mma_gemm_h<<<grid, 256, DYN_SMEM>>>(A, WT, nullptr, nullptr, C, M, N, K);
}

extern "C" void kernel_launch(void* const* d_in, const int* in_sizes, int n_in,
                              void* d_out, int out_size) {
    cudaFuncSetAttribute(mma_gemm_h, cudaFuncAttributeMaxDynamicSharedMemorySize, DYN_SMEM);

    const float* x_gnn = (const float*)d_in[0];
    const int*   eidx  = (const int*)d_in[1];
    const float* eattr = (const float*)d_in[2];
    const float* W_in  = (const float*)d_in[3];
    const float* b_in  = (const float*)d_in[4];
    const float* Wl1   = (const float*)d_in[5];
    const float* Wr1   = (const float*)d_in[6];
    const float* We1   = (const float*)d_in[7];
    const float* att1  = (const float*)d_in[8];
    const float* bg1   = (const float*)d_in[9];
    const float* ln1_g = (const float*)d_in[10];
    const float* ln1_b = (const float*)d_in[11];
    const float* W_down= (const float*)d_in[12];
    const float* lnd_g = (const float*)d_in[13];
    const float* lnd_b = (const float*)d_in[14];
    const float* Wl2   = (const float*)d_in[15];
    const float* Wr2   = (const float*)d_in[16];
    const float* We2   = (const float*)d_in[17];
    const float* att2  = (const float*)d_in[18];
    const float* bg2   = (const float*)d_in[19];
    const float* ln2_g = (const float*)d_in[20];
    const float* ln2_b = (const float*)d_in[21];
    const float* W_up  = (const float*)d_in[22];
    const float* lnu_g = (const float*)d_in[23];
    const float* lnu_b = (const float*)d_in[24];
    const float* W_cls = (const float*)d_in[25];
    const float* b_cls = (const float*)d_in[26];

    const int n = in_sizes[0] / 18;        // 20000
    const int E = in_sizes[1] / 2;         // 320000
    const int* src = eidx;
    const int* dst = eidx + E;

    float *h1, *z, *tmp;
    __half *xlr, *h0h, *h1h, *zh, *z2h, *outh, *wth;
    int *head;
    int4 *enode;
    cudaGetSymbolAddress((void**)&xlr, g_xlr);
    cudaGetSymbolAddress((void**)&h1, g_h1);
    cudaGetSymbolAddress((void**)&z, g_z);
    cudaGetSymbolAddress((void**)&tmp, g_tmp);
    cudaGetSymbolAddress((void**)&h0h, g_h0h);
    cudaGetSymbolAddress((void**)&h1h, g_h1h);
    cudaGetSymbolAddress((void**)&zh, g_zh);
    cudaGetSymbolAddress((void**)&z2h, g_z2h);
    cudaGetSymbolAddress((void**)&outh, g_outh);
    cudaGetSymbolAddress((void**)&wth, g_wth);
    cudaGetSymbolAddress((void**)&head, g_head);
    cudaGetSymbolAddress((void**)&enode, g_enode);

    float* out_logits = (float*)d_out;
    float* out_h = (float*)d_out + (size_t)n * 1000;

    const int lnBlocks = (n + 7) / 8;
    const int nodeBlocks = (n + 7) / 8;

    // ---- fused prologue: head=-1 + weight transposes + input projection ----
    {
        PrologueArgs pa;
        auto set = [&](int i, const float* in, __half* out, int Kreal, int Kpad, int N, int& cum) {
            pa.d[i].in = in; pa.d[i].out = out;
            pa.d[i].Kreal = Kreal; pa.d[i].Kpad = Kpad; pa.d[i].N = N;
            pa.d[i].blkStart = cum; pa.d[i].nx = (N + 31) / 32;
            cum += pa.d[i].nx * ((Kpad + 31) / 32);
        };
        int cum = 0;
        set(0, Wl1,    wth + WTH_L1,            32, 64, DIM, cum);
        set(1, Wr1,    wth + WTH_L1 + 256 * 64, 32, 64, DIM, cum);
        set(2, W_down, wth + WTH_DN,  DIM, DIM, DIM, cum);
        set(3, Wl2,    wth + WTH_L2,  DIM, DIM, DIM, cum);
        set(4, Wr2,    wth + WTH_L2 + 256 * 256, DIM, DIM, DIM, cum);
        set(5, W_up,   wth + WTH_UP,  DIM, DIM, DIM, cum);
        set(6, W_cls,  wth + WTH_CLS, DIM, DIM, 1000, cum);
        pa.tcum = cum;
        pa.zb = (n + 255) / 256;
        pa.head = head;
        pa.x = x_gnn; pa.W_in = W_in; pa.b_in = b_in; pa.h0h = h0h;
        pa.n = n;
        int total = pa.zb + cum + (n + 7) / 8;
        prologue_kernel<<<total, 256>>>(pa);
    }

    // ---- GAT layer 1 GEMM (independent of edge list) ----
    launch_tgemm16(h0h, wth + WTH_L1, xlr, n, 512, 64);

    // ---- linked-list build ----
    list_build_kernel<<<(E + 255) / 256, 256>>>(src, dst, eattr, head, enode, E);

    // ---- GAT layer 1 gather+LN ----
    gatln_kernel<<<nodeBlocks, 256>>>(xlr, head, enode, We1, att1, bg1,
                                      nullptr, ln1_g, ln1_b, h1, h1h, n);

    // ---- bottleneck down ----
    launch_tgemm32(h1h, wth + WTH_DN, nullptr, tmp, n, DIM, DIM);
    ln_kernel<<<lnBlocks, 256>>>(tmp, nullptr, lnd_g, lnd_b, z, zh, n);

    // ---- GAT layer 2 (residual z inside fused gather-LN) ----
    launch_tgemm16(zh, wth + WTH_L2, xlr, n, 512, DIM);
    gatln_kernel<<<nodeBlocks, 256>>>(xlr, head, enode, We2, att2, bg2,
                                      z, ln2_g, ln2_b, nullptr, z2h, n);

    // ---- up projection + final LN ----
    launch_tgemm32(z2h, wth + WTH_UP, nullptr, tmp, n, DIM, DIM);
    ln_kernel<<<lnBlocks, 256>>>(tmp, h1, lnu_g, lnu_b, out_h, outh, n);

    // ---- classifier ----
    launch_tgemm32(outh, wth + WTH_CLS, b_cls, out_logits, n, 1000, DIM);
}